// round 1
// baseline (speedup 1.0000x reference)
#include <cuda_runtime.h>
#include <math.h>

// ---------------- problem constants ----------------
#define NROWS 50000
#define FIN   1024
#define HIDD  256
#define OUTF  280
#define SROWS 5000
#define NNZE  800000

// ---------------- scratch (static device globals; no allocation) ----------------
__device__ __align__(256) float g_h0 [(size_t)NROWS*HIDD];   // post-BN features
__device__ __align__(256) float g_z  [(size_t)NROWS*HIDD];   // GEMM temp
__device__ __align__(256) float g_t  [(size_t)NROWS*HIDD];   // spmm temp
__device__ __align__(256) float g_zd [(size_t)NROWS*OUTF];   // dgi pre-spmm
__device__ __align__(256) float g_s1 [(size_t)NROWS*OUTF];   // h1
__device__ __align__(256) float g_s2 [(size_t)NROWS*OUTF];   // h2
__device__ __align__(256) float g_agg[(size_t)SROWS*OUTF];
__device__ __align__(256) float g_stats[2*HIDD];
__device__ __align__(256) float g_scale[HIDD];
__device__ __align__(256) float g_shift[HIDD];
__device__ __align__(256) float g_c  [OUTF];
__device__ __align__(256) float g_acc[4];                    // mse_sum, t1_sum, t2_sum, c_norm
__device__ __align__(256) int   g_pcols[NNZE];

enum { ACT_NONE = 0, ACT_LEAKY = 1, ACT_PRELU = 2 };

// ---------------- 128x128x8 fp32 SGEMM with fused bias + activation ----------------
template<int ACT>
__global__ __launch_bounds__(256)
void sgemm_kernel(const float* __restrict__ A, const float* __restrict__ B,
                  const float* __restrict__ bias, float* __restrict__ C,
                  int M, int N, int K, float slope, const float* __restrict__ alpha_ptr)
{
    constexpr int BM = 128, BN = 128, BK = 8;
    __shared__ float As[BK][BM];
    __shared__ float Bs[BK][BN];

    const int tid = threadIdx.x;
    const int bm = blockIdx.y * BM;
    const int bn = blockIdx.x * BN;

    const int a_row = tid >> 1;          // 0..127
    const int a_col = (tid & 1) << 2;    // 0 or 4
    const int b_row = tid >> 5;          // 0..7
    const int b_col = (tid & 31) << 2;   // 0..124

    const int tx = tid & 15;
    const int ty = tid >> 4;

    float acc[8][8];
#pragma unroll
    for (int i = 0; i < 8; i++)
#pragma unroll
        for (int j = 0; j < 8; j++) acc[i][j] = 0.f;

    const bool a_valid = (bm + a_row) < M;
    const int  bn_g    = bn + b_col;
    const bool b_valid = bn_g < N;       // N % 4 == 0 for all our GEMMs
    const float* Ap = A + (size_t)(bm + a_row) * K + a_col;
    const float* Bp = B + (size_t)b_row * N + bn_g;

    for (int k0 = 0; k0 < K; k0 += BK) {
        float4 av = make_float4(0.f, 0.f, 0.f, 0.f);
        if (a_valid) av = *reinterpret_cast<const float4*>(Ap + k0);
        As[a_col + 0][a_row] = av.x;
        As[a_col + 1][a_row] = av.y;
        As[a_col + 2][a_row] = av.z;
        As[a_col + 3][a_row] = av.w;

        float4 bv = make_float4(0.f, 0.f, 0.f, 0.f);
        if (b_valid) bv = *reinterpret_cast<const float4*>(Bp + (size_t)k0 * N);
        *reinterpret_cast<float4*>(&Bs[b_row][b_col]) = bv;

        __syncthreads();
#pragma unroll
        for (int k = 0; k < BK; k++) {
            float af[8], bf[8];
            *reinterpret_cast<float4*>(&af[0]) = *reinterpret_cast<const float4*>(&As[k][ty * 8]);
            *reinterpret_cast<float4*>(&af[4]) = *reinterpret_cast<const float4*>(&As[k][ty * 8 + 4]);
            *reinterpret_cast<float4*>(&bf[0]) = *reinterpret_cast<const float4*>(&Bs[k][tx * 8]);
            *reinterpret_cast<float4*>(&bf[4]) = *reinterpret_cast<const float4*>(&Bs[k][tx * 8 + 4]);
#pragma unroll
            for (int i = 0; i < 8; i++)
#pragma unroll
                for (int j = 0; j < 8; j++)
                    acc[i][j] = fmaf(af[i], bf[j], acc[i][j]);
        }
        __syncthreads();
    }

    float alpha = slope;
    if (ACT == ACT_PRELU) alpha = *alpha_ptr;
#pragma unroll
    for (int i = 0; i < 8; i++) {
        int r = bm + ty * 8 + i;
        if (r < M) {
#pragma unroll
            for (int j = 0; j < 8; j++) {
                int cc = bn + tx * 8 + j;
                if (cc < N) {
                    float v = acc[i][j] + bias[cc];
                    if (ACT != ACT_NONE) v = (v >= 0.f) ? v : alpha * v;
                    C[(size_t)r * N + cc] = v;
                }
            }
        }
    }
}

// ---------------- BN ----------------
__global__ void bn_stats_kernel(const float* __restrict__ H, float* __restrict__ stats)
{
    const int col = threadIdx.x;  // 256 threads
    const int rpb = (NROWS + gridDim.x - 1) / gridDim.x;
    const int r0 = blockIdx.x * rpb;
    const int r1 = min(NROWS, r0 + rpb);
    float s = 0.f, ss = 0.f;
    for (int r = r0; r < r1; r++) {
        float v = H[(size_t)r * HIDD + col];
        s += v;
        ss = fmaf(v, v, ss);
    }
    atomicAdd(&stats[col], s);
    atomicAdd(&stats[HIDD + col], ss);
}

__global__ void bn_finalize_kernel(const float* __restrict__ stats,
                                   const float* __restrict__ gamma,
                                   const float* __restrict__ beta,
                                   float* __restrict__ scale, float* __restrict__ shift)
{
    int c = threadIdx.x;
    float mu  = stats[c] * (1.0f / NROWS);
    float var = stats[HIDD + c] * (1.0f / NROWS) - mu * mu;
    float sc  = gamma[c] * rsqrtf(var + 1e-5f);
    scale[c] = sc;
    shift[c] = beta[c] - mu * sc;
}

__global__ void bn_apply_kernel(const float* __restrict__ in, float* __restrict__ outp,
                                const float* __restrict__ scale, const float* __restrict__ shift)
{
    int i = blockIdx.x * blockDim.x + threadIdx.x;
    if (i < NROWS * HIDD) {
        int c = i & (HIDD - 1);
        outp[i] = fmaf(in[i], scale[c], shift[c]);
    }
}

// ---------------- SpMM (scatter-add) ----------------
template<int F>
__global__ void spmm_kernel(const int* __restrict__ rows, const int* __restrict__ cols,
                            const float* __restrict__ vals, const float* __restrict__ Msrc,
                            float* __restrict__ Out)
{
    long long idx = (long long)blockIdx.x * blockDim.x + threadIdx.x;
    if (idx >= (long long)NNZE * F) return;
    int e = (int)(idx / F);
    int f = (int)(idx - (long long)e * F);
    float v = vals[e] * Msrc[(size_t)cols[e] * F + f];
    atomicAdd(&Out[(size_t)rows[e] * F + f], v);
}

__global__ void permcols_kernel(const int* __restrict__ cols, const int* __restrict__ perm,
                                int* __restrict__ pcols)
{
    int e = blockIdx.x * blockDim.x + threadIdx.x;
    if (e < NNZE) pcols[e] = perm[cols[e]];
}

// ---------------- elementwise activations ----------------
__global__ void act_leaky_kernel(float* p, int n, float slope)
{
    int i = blockIdx.x * blockDim.x + threadIdx.x;
    if (i < n) {
        float v = p[i];
        p[i] = (v >= 0.f) ? v : slope * v;
    }
}

__global__ void act_prelu_kernel(float* p, int n, const float* __restrict__ a)
{
    int i = blockIdx.x * blockDim.x + threadIdx.x;
    if (i < n) {
        float al = *a;
        float v = p[i];
        p[i] = (v >= 0.f) ? v : al * v;
    }
}

// ---------------- agg scatter + MSE ----------------
__global__ void agg_kernel(const int* __restrict__ arows, const float* __restrict__ avals,
                           const float* __restrict__ xp, float* __restrict__ agg)
{
    int idx = blockIdx.x * blockDim.x + threadIdx.x;
    if (idx < NROWS * OUTF) {
        int i = idx / OUTF;
        int f = idx - i * OUTF;
        atomicAdd(&agg[(size_t)arows[i] * OUTF + f], avals[i] * xp[idx]);
    }
}

__global__ void mse_kernel(const float* __restrict__ agg, const float* __restrict__ y,
                           float* __restrict__ acc)
{
    __shared__ float sh[256];
    float s = 0.f;
    for (int idx = blockIdx.x * blockDim.x + threadIdx.x; idx < SROWS * OUTF;
         idx += gridDim.x * blockDim.x) {
        float d = agg[idx] - y[idx];
        s = fmaf(d, d, s);
    }
    sh[threadIdx.x] = s;
    __syncthreads();
    for (int o = 128; o; o >>= 1) {
        if (threadIdx.x < o) sh[threadIdx.x] += sh[threadIdx.x + o];
        __syncthreads();
    }
    if (threadIdx.x == 0) atomicAdd(&acc[0], sh[0]);
}

// ---------------- DGI summary vector + cosine terms ----------------
__global__ void colsum_kernel(const float* __restrict__ H, float* __restrict__ sums)
{
    const int rpb = (NROWS + gridDim.x - 1) / gridDim.x;
    const int r0 = blockIdx.x * rpb;
    const int r1 = min(NROWS, r0 + rpb);
    for (int c = threadIdx.x; c < OUTF; c += blockDim.x) {
        float s = 0.f;
        for (int r = r0; r < r1; r++) s += H[(size_t)r * OUTF + c];
        atomicAdd(&sums[c], s);
    }
}

__global__ void c_finalize_kernel(float* __restrict__ c, float* __restrict__ acc)
{
    __shared__ float sh[512];
    int t = threadIdx.x;
    float v = 0.f;
    if (t < OUTF) {
        float m = c[t] * (1.0f / NROWS);
        c[t] = m;
        v = m * m;
    }
    sh[t] = v;
    __syncthreads();
    for (int o = 256; o; o >>= 1) {
        if (t < o) sh[t] += sh[t + o];
        __syncthreads();
    }
    if (t == 0) acc[3] = sqrtf(sh[0]);
}

__global__ void cos_kernel(const float* __restrict__ h1, const float* __restrict__ h2,
                           const float* __restrict__ c, float* __restrict__ acc)
{
    const int warp = threadIdx.x >> 5;
    const int lane = threadIdx.x & 31;
    const int row = blockIdx.x * 8 + warp;
    float t1 = 0.f, t2 = 0.f;
    if (row < NROWS) {
        float d1 = 0.f, n1 = 0.f, d2 = 0.f, n2 = 0.f;
        const float* r1 = h1 + (size_t)row * OUTF;
        const float* r2 = h2 + (size_t)row * OUTF;
        for (int f = lane; f < OUTF; f += 32) {
            float cf = c[f];
            float v1 = r1[f], v2 = r2[f];
            d1 = fmaf(v1, cf, d1);
            n1 = fmaf(v1, v1, n1);
            d2 = fmaf(v2, cf, d2);
            n2 = fmaf(v2, v2, n2);
        }
#pragma unroll
        for (int o = 16; o; o >>= 1) {
            d1 += __shfl_down_sync(0xffffffffu, d1, o);
            n1 += __shfl_down_sync(0xffffffffu, n1, o);
            d2 += __shfl_down_sync(0xffffffffu, d2, o);
            n2 += __shfl_down_sync(0xffffffffu, n2, o);
        }
        if (lane == 0) {
            float cn = acc[3];
            float cos1 = d1 / fmaxf(sqrtf(n1) * cn, 1e-8f);
            float cos2 = d2 / fmaxf(sqrtf(n2) * cn, 1e-8f);
            t1 = 1.f - cos1;
            t2 = fmaxf(cos2, 0.f);
        }
    }
    __shared__ float sh1[8], sh2[8];
    if (lane == 0) { sh1[warp] = t1; sh2[warp] = t2; }
    __syncthreads();
    if (threadIdx.x == 0) {
        float a = 0.f, b = 0.f;
#pragma unroll
        for (int w = 0; w < 8; w++) { a += sh1[w]; b += sh2[w]; }
        atomicAdd(&acc[1], a);
        atomicAdd(&acc[2], b);
    }
}

__global__ void final_kernel(const float* __restrict__ acc, float* __restrict__ out)
{
    out[0] = acc[0] * (1.0f / (SROWS * OUTF))
           + acc[1] * (1.0f / NROWS)
           + acc[2] * (1.0f / NROWS);
}

// ---------------- host ----------------
static inline int cdiv(int a, int b) { return (a + b - 1) / b; }

extern "C" void kernel_launch(void* const* d_in, const int* in_sizes, int n_in,
                              void* d_out_v, int out_size)
{
    (void)in_sizes; (void)n_in; (void)out_size;

    const float* x         = (const float*)d_in[0];
    const float* y         = (const float*)d_in[1];
    const int*   adj_rows  = (const int*)d_in[2];
    const int*   adj_cols  = (const int*)d_in[3];
    const float* adj_vals  = (const float*)d_in[4];
    const int*   agg_rows  = (const int*)d_in[5];
    const float* agg_vals  = (const float*)d_in[6];
    const int*   perm      = (const int*)d_in[7];
    const float* mlp_W     = (const float*)d_in[8];
    const float* mlp_b     = (const float*)d_in[9];
    const float* bn_gamma  = (const float*)d_in[10];
    const float* bn_beta   = (const float*)d_in[11];
    const float* hg_W1     = (const float*)d_in[12];
    const float* hg_b1     = (const float*)d_in[13];
    const float* hg_W2     = (const float*)d_in[14];
    const float* hg_b2     = (const float*)d_in[15];
    const float* hg_prelu  = (const float*)d_in[16];
    const float* pred_W    = (const float*)d_in[17];
    const float* pred_b    = (const float*)d_in[18];
    const float* dgi_W     = (const float*)d_in[19];
    const float* dgi_b     = (const float*)d_in[20];
    const float* dgi_prelu = (const float*)d_in[21];

    float* out = (float*)d_out_v;
    float* xp  = out + 1;  // x_prime: (50000, 280), loss at out[0]

    float *h0, *z, *t, *zd, *s1, *s2, *agg, *stats, *scale, *shift, *cbuf, *acc;
    int* pcols;
    cudaGetSymbolAddress((void**)&h0,    g_h0);
    cudaGetSymbolAddress((void**)&z,     g_z);
    cudaGetSymbolAddress((void**)&t,     g_t);
    cudaGetSymbolAddress((void**)&zd,    g_zd);
    cudaGetSymbolAddress((void**)&s1,    g_s1);
    cudaGetSymbolAddress((void**)&s2,    g_s2);
    cudaGetSymbolAddress((void**)&agg,   g_agg);
    cudaGetSymbolAddress((void**)&stats, g_stats);
    cudaGetSymbolAddress((void**)&scale, g_scale);
    cudaGetSymbolAddress((void**)&shift, g_shift);
    cudaGetSymbolAddress((void**)&cbuf,  g_c);
    cudaGetSymbolAddress((void**)&acc,   g_acc);
    cudaGetSymbolAddress((void**)&pcols, g_pcols);

    cudaStream_t st = 0;
    const dim3 gH(cdiv(HIDD, 128), cdiv(NROWS, 128));   // N=256 tiles
    const dim3 gO(cdiv(OUTF, 128), cdiv(NROWS, 128));   // N=280 tiles

    // ---- MLP: leaky(x @ mlp_W + b, 0.1) ----
    sgemm_kernel<ACT_LEAKY><<<gH, 256, 0, st>>>(x, mlp_W, mlp_b, z, NROWS, HIDD, FIN, 0.1f, nullptr);

    // ---- BatchNorm (training stats) ----
    cudaMemsetAsync(stats, 0, 2 * HIDD * sizeof(float), st);
    bn_stats_kernel<<<256, 256, 0, st>>>(z, stats);
    bn_finalize_kernel<<<1, HIDD, 0, st>>>(stats, bn_gamma, bn_beta, scale, shift);
    bn_apply_kernel<<<cdiv(NROWS * HIDD, 256), 256, 0, st>>>(z, h0, scale, shift);

    // ---- HGNN layer 1 ----
    sgemm_kernel<ACT_NONE><<<gH, 256, 0, st>>>(h0, hg_W1, hg_b1, z, NROWS, HIDD, HIDD, 0.f, nullptr);
    cudaMemsetAsync(t, 0, (size_t)NROWS * HIDD * sizeof(float), st);
    spmm_kernel<HIDD><<<cdiv(NNZE * HIDD, 256), 256, 0, st>>>(adj_rows, adj_cols, adj_vals, z, t);
    act_prelu_kernel<<<cdiv(NROWS * HIDD, 256), 256, 0, st>>>(t, NROWS * HIDD, hg_prelu);

    // ---- HGNN layer 2 ----
    sgemm_kernel<ACT_NONE><<<gH, 256, 0, st>>>(t, hg_W2, hg_b2, z, NROWS, HIDD, HIDD, 0.f, nullptr);
    cudaMemsetAsync(t, 0, (size_t)NROWS * HIDD * sizeof(float), st);
    spmm_kernel<HIDD><<<cdiv(NNZE * HIDD, 256), 256, 0, st>>>(adj_rows, adj_cols, adj_vals, z, t);
    act_leaky_kernel<<<cdiv(NROWS * HIDD, 256), 256, 0, st>>>(t, NROWS * HIDD, 0.01f);

    // ---- prediction head: x_prime = leaky(h @ pred_W + b, 0.01) ----
    sgemm_kernel<ACT_LEAKY><<<gO, 256, 0, st>>>(t, pred_W, pred_b, xp, NROWS, OUTF, HIDD, 0.01f, nullptr);

    // ---- Xenium MSE: agg = segment_sum(agg_vals * x_prime) ----
    cudaMemsetAsync(agg, 0, (size_t)SROWS * OUTF * sizeof(float), st);
    cudaMemsetAsync(acc, 0, 4 * sizeof(float), st);
    agg_kernel<<<cdiv(NROWS * OUTF, 256), 256, 0, st>>>(agg_rows, agg_vals, xp, agg);
    mse_kernel<<<2048, 256, 0, st>>>(agg, y, acc);

    // ---- DGI: zd = h0 @ dgi_W + b (perm branch reuses zd via perm∘cols) ----
    sgemm_kernel<ACT_NONE><<<gO, 256, 0, st>>>(h0, dgi_W, dgi_b, zd, NROWS, OUTF, HIDD, 0.f, nullptr);
    permcols_kernel<<<cdiv(NNZE, 256), 256, 0, st>>>(adj_cols, perm, pcols);
    cudaMemsetAsync(s1, 0, (size_t)NROWS * OUTF * sizeof(float), st);
    cudaMemsetAsync(s2, 0, (size_t)NROWS * OUTF * sizeof(float), st);
    spmm_kernel<OUTF><<<cdiv(NNZE * OUTF, 256), 256, 0, st>>>(adj_rows, adj_cols, adj_vals, zd, s1);
    spmm_kernel<OUTF><<<cdiv(NNZE * OUTF, 256), 256, 0, st>>>(adj_rows, pcols, adj_vals, zd, s2);
    act_prelu_kernel<<<cdiv(NROWS * OUTF, 256), 256, 0, st>>>(s1, NROWS * OUTF, dgi_prelu);
    act_prelu_kernel<<<cdiv(NROWS * OUTF, 256), 256, 0, st>>>(s2, NROWS * OUTF, dgi_prelu);

    // ---- summary vector c, norm, cosine terms ----
    cudaMemsetAsync(cbuf, 0, OUTF * sizeof(float), st);
    colsum_kernel<<<256, 256, 0, st>>>(s1, cbuf);
    c_finalize_kernel<<<1, 512, 0, st>>>(cbuf, acc);
    cos_kernel<<<cdiv(NROWS, 8), 256, 0, st>>>(s1, s2, cbuf, acc);

    // ---- final loss ----
    final_kernel<<<1, 1, 0, st>>>(acc, out);
}

// round 2
// speedup vs baseline: 1.0298x; 1.0298x over previous
#include <cuda_runtime.h>
#include <math.h>

// ---------------- problem constants ----------------
#define NROWS 50000
#define FIN   1024
#define HIDD  256
#define OUTF  280
#define SROWS 5000
#define NNZE  800000

// ---------------- scratch (static device globals; no allocation) ----------------
__device__ __align__(256) float g_h0 [(size_t)NROWS*HIDD];   // post-BN features
__device__ __align__(256) float g_z  [(size_t)NROWS*HIDD];   // GEMM temp
__device__ __align__(256) float g_t  [(size_t)NROWS*HIDD];   // spmm temp
__device__ __align__(256) float g_zd [(size_t)NROWS*OUTF];   // dgi pre-spmm
__device__ __align__(256) float g_s1 [(size_t)NROWS*OUTF];   // h1
__device__ __align__(256) float g_s2 [(size_t)NROWS*OUTF];   // h2
__device__ __align__(256) float g_agg[(size_t)SROWS*OUTF];
__device__ __align__(256) float g_stats[2*HIDD];
__device__ __align__(256) float g_scale[HIDD];
__device__ __align__(256) float g_shift[HIDD];
__device__ __align__(256) float g_c  [OUTF];
__device__ __align__(256) float g_acc[4];                    // mse_sum, t1_sum, t2_sum, c_norm
__device__ __align__(256) int   g_pcols[NNZE];

enum { ACT_NONE = 0, ACT_LEAKY = 1, ACT_PRELU = 2 };

// ---------------- 128x128x8 fp32 SGEMM with fused bias + activation ----------------
template<int ACT>
__global__ __launch_bounds__(256)
void sgemm_kernel(const float* __restrict__ A, const float* __restrict__ B,
                  const float* __restrict__ bias, float* __restrict__ C,
                  int M, int N, int K, float slope, const float* __restrict__ alpha_ptr)
{
    constexpr int BM = 128, BN = 128, BK = 8;
    __shared__ float As[BK][BM];
    __shared__ float Bs[BK][BN];

    const int tid = threadIdx.x;
    const int bm = blockIdx.y * BM;
    const int bn = blockIdx.x * BN;

    const int a_row = tid >> 1;          // 0..127
    const int a_col = (tid & 1) << 2;    // 0 or 4
    const int b_row = tid >> 5;          // 0..7
    const int b_col = (tid & 31) << 2;   // 0..124

    const int tx = tid & 15;
    const int ty = tid >> 4;

    float acc[8][8];
#pragma unroll
    for (int i = 0; i < 8; i++)
#pragma unroll
        for (int j = 0; j < 8; j++) acc[i][j] = 0.f;

    const bool a_valid = (bm + a_row) < M;
    const int  bn_g    = bn + b_col;
    const bool b_valid = bn_g < N;       // N % 4 == 0 for all our GEMMs
    const float* Ap = A + (size_t)(bm + a_row) * K + a_col;
    const float* Bp = B + (size_t)b_row * N + bn_g;

    for (int k0 = 0; k0 < K; k0 += BK) {
        float4 av = make_float4(0.f, 0.f, 0.f, 0.f);
        if (a_valid) av = *reinterpret_cast<const float4*>(Ap + k0);
        As[a_col + 0][a_row] = av.x;
        As[a_col + 1][a_row] = av.y;
        As[a_col + 2][a_row] = av.z;
        As[a_col + 3][a_row] = av.w;

        float4 bv = make_float4(0.f, 0.f, 0.f, 0.f);
        if (b_valid) bv = *reinterpret_cast<const float4*>(Bp + (size_t)k0 * N);
        *reinterpret_cast<float4*>(&Bs[b_row][b_col]) = bv;

        __syncthreads();
#pragma unroll
        for (int k = 0; k < BK; k++) {
            float af[8], bf[8];
            *reinterpret_cast<float4*>(&af[0]) = *reinterpret_cast<const float4*>(&As[k][ty * 8]);
            *reinterpret_cast<float4*>(&af[4]) = *reinterpret_cast<const float4*>(&As[k][ty * 8 + 4]);
            *reinterpret_cast<float4*>(&bf[0]) = *reinterpret_cast<const float4*>(&Bs[k][tx * 8]);
            *reinterpret_cast<float4*>(&bf[4]) = *reinterpret_cast<const float4*>(&Bs[k][tx * 8 + 4]);
#pragma unroll
            for (int i = 0; i < 8; i++)
#pragma unroll
                for (int j = 0; j < 8; j++)
                    acc[i][j] = fmaf(af[i], bf[j], acc[i][j]);
        }
        __syncthreads();
    }

    float alpha = slope;
    if (ACT == ACT_PRELU) alpha = *alpha_ptr;
#pragma unroll
    for (int i = 0; i < 8; i++) {
        int r = bm + ty * 8 + i;
        if (r < M) {
#pragma unroll
            for (int j = 0; j < 8; j++) {
                int cc = bn + tx * 8 + j;
                if (cc < N) {
                    float v = acc[i][j] + bias[cc];
                    if (ACT != ACT_NONE) v = (v >= 0.f) ? v : alpha * v;
                    C[(size_t)r * N + cc] = v;
                }
            }
        }
    }
}

// ---------------- BN ----------------
__global__ void bn_stats_kernel(const float* __restrict__ H, float* __restrict__ stats)
{
    const int col = threadIdx.x;  // 256 threads
    const int rpb = (NROWS + gridDim.x - 1) / gridDim.x;
    const int r0 = blockIdx.x * rpb;
    const int r1 = min(NROWS, r0 + rpb);
    float s = 0.f, ss = 0.f;
    for (int r = r0; r < r1; r++) {
        float v = H[(size_t)r * HIDD + col];
        s += v;
        ss = fmaf(v, v, ss);
    }
    atomicAdd(&stats[col], s);
    atomicAdd(&stats[HIDD + col], ss);
}

__global__ void bn_finalize_kernel(const float* __restrict__ stats,
                                   const float* __restrict__ gamma,
                                   const float* __restrict__ beta,
                                   float* __restrict__ scale, float* __restrict__ shift)
{
    int c = threadIdx.x;
    float mu  = stats[c] * (1.0f / NROWS);
    float var = stats[HIDD + c] * (1.0f / NROWS) - mu * mu;
    float sc  = gamma[c] * rsqrtf(var + 1e-5f);
    scale[c] = sc;
    shift[c] = beta[c] - mu * sc;
}

__global__ void bn_apply_kernel(const float* __restrict__ in, float* __restrict__ outp,
                                const float* __restrict__ scale, const float* __restrict__ shift)
{
    int i = blockIdx.x * blockDim.x + threadIdx.x;
    if (i < NROWS * HIDD) {
        int c = i & (HIDD - 1);
        outp[i] = fmaf(in[i], scale[c], shift[c]);
    }
}

// ---------------- SpMM (scatter-add) ----------------
template<int F>
__global__ void spmm_kernel(const int* __restrict__ rows, const int* __restrict__ cols,
                            const float* __restrict__ vals, const float* __restrict__ Msrc,
                            float* __restrict__ Out)
{
    long long idx = (long long)blockIdx.x * blockDim.x + threadIdx.x;
    if (idx >= (long long)NNZE * F) return;
    int e = (int)(idx / F);
    int f = (int)(idx - (long long)e * F);
    float v = vals[e] * Msrc[(size_t)cols[e] * F + f];
    atomicAdd(&Out[(size_t)rows[e] * F + f], v);
}

__global__ void permcols_kernel(const int* __restrict__ cols, const int* __restrict__ perm,
                                int* __restrict__ pcols)
{
    int e = blockIdx.x * blockDim.x + threadIdx.x;
    if (e < NNZE) pcols[e] = perm[cols[e]];
}

// ---------------- elementwise activations ----------------
__global__ void act_leaky_kernel(float* p, int n, float slope)
{
    int i = blockIdx.x * blockDim.x + threadIdx.x;
    if (i < n) {
        float v = p[i];
        p[i] = (v >= 0.f) ? v : slope * v;
    }
}

__global__ void act_prelu_kernel(float* p, int n, const float* __restrict__ a)
{
    int i = blockIdx.x * blockDim.x + threadIdx.x;
    if (i < n) {
        float al = *a;
        float v = p[i];
        p[i] = (v >= 0.f) ? v : al * v;
    }
}

// ---------------- agg scatter + MSE ----------------
__global__ void agg_kernel(const int* __restrict__ arows, const float* __restrict__ avals,
                           const float* __restrict__ xp, float* __restrict__ agg)
{
    int idx = blockIdx.x * blockDim.x + threadIdx.x;
    if (idx < NROWS * OUTF) {
        int i = idx / OUTF;
        int f = idx - i * OUTF;
        atomicAdd(&agg[(size_t)arows[i] * OUTF + f], avals[i] * xp[idx]);
    }
}

__global__ void mse_kernel(const float* __restrict__ agg, const float* __restrict__ y,
                           float* __restrict__ acc)
{
    __shared__ float sh[256];
    float s = 0.f;
    for (int idx = blockIdx.x * blockDim.x + threadIdx.x; idx < SROWS * OUTF;
         idx += gridDim.x * blockDim.x) {
        float d = agg[idx] - y[idx];
        s = fmaf(d, d, s);
    }
    sh[threadIdx.x] = s;
    __syncthreads();
    for (int o = 128; o; o >>= 1) {
        if (threadIdx.x < o) sh[threadIdx.x] += sh[threadIdx.x + o];
        __syncthreads();
    }
    if (threadIdx.x == 0) atomicAdd(&acc[0], sh[0]);
}

// ---------------- DGI summary vector + cosine terms ----------------
__global__ void colsum_kernel(const float* __restrict__ H, float* __restrict__ sums)
{
    const int rpb = (NROWS + gridDim.x - 1) / gridDim.x;
    const int r0 = blockIdx.x * rpb;
    const int r1 = min(NROWS, r0 + rpb);
    for (int c = threadIdx.x; c < OUTF; c += blockDim.x) {
        float s = 0.f;
        for (int r = r0; r < r1; r++) s += H[(size_t)r * OUTF + c];
        atomicAdd(&sums[c], s);
    }
}

__global__ void c_finalize_kernel(float* __restrict__ c, float* __restrict__ acc)
{
    __shared__ float sh[512];
    int t = threadIdx.x;
    float v = 0.f;
    if (t < OUTF) {
        float m = c[t] * (1.0f / NROWS);
        c[t] = m;
        v = m * m;
    }
    sh[t] = v;
    __syncthreads();
    for (int o = 256; o; o >>= 1) {
        if (t < o) sh[t] += sh[t + o];
        __syncthreads();
    }
    if (t == 0) acc[3] = sqrtf(sh[0]);
}

__global__ void cos_kernel(const float* __restrict__ h1, const float* __restrict__ h2,
                           const float* __restrict__ c, float* __restrict__ acc)
{
    const int warp = threadIdx.x >> 5;
    const int lane = threadIdx.x & 31;
    const int row = blockIdx.x * 8 + warp;
    float t1 = 0.f, t2 = 0.f;
    if (row < NROWS) {
        float d1 = 0.f, n1 = 0.f, d2 = 0.f, n2 = 0.f;
        const float* r1 = h1 + (size_t)row * OUTF;
        const float* r2 = h2 + (size_t)row * OUTF;
        for (int f = lane; f < OUTF; f += 32) {
            float cf = c[f];
            float v1 = r1[f], v2 = r2[f];
            d1 = fmaf(v1, cf, d1);
            n1 = fmaf(v1, v1, n1);
            d2 = fmaf(v2, cf, d2);
            n2 = fmaf(v2, v2, n2);
        }
#pragma unroll
        for (int o = 16; o; o >>= 1) {
            d1 += __shfl_down_sync(0xffffffffu, d1, o);
            n1 += __shfl_down_sync(0xffffffffu, n1, o);
            d2 += __shfl_down_sync(0xffffffffu, d2, o);
            n2 += __shfl_down_sync(0xffffffffu, n2, o);
        }
        if (lane == 0) {
            float cn = acc[3];
            float cos1 = d1 / fmaxf(sqrtf(n1) * cn, 1e-8f);
            float cos2 = d2 / fmaxf(sqrtf(n2) * cn, 1e-8f);
            t1 = 1.f - cos1;
            t2 = fmaxf(cos2, 0.f);
        }
    }
    __shared__ float sh1[8], sh2[8];
    if (lane == 0) { sh1[warp] = t1; sh2[warp] = t2; }
    __syncthreads();
    if (threadIdx.x == 0) {
        float a = 0.f, b = 0.f;
#pragma unroll
        for (int w = 0; w < 8; w++) { a += sh1[w]; b += sh2[w]; }
        atomicAdd(&acc[1], a);
        atomicAdd(&acc[2], b);
    }
}

__global__ void final_kernel(const float* __restrict__ acc, float* __restrict__ out)
{
    out[0] = acc[0] * (1.0f / (SROWS * OUTF))
           + acc[1] * (1.0f / NROWS)
           + acc[2] * (1.0f / NROWS);
}

// ---------------- host ----------------
static inline int cdiv(int a, int b) { return (a + b - 1) / b; }

extern "C" void kernel_launch(void* const* d_in, const int* in_sizes, int n_in,
                              void* d_out_v, int out_size)
{
    (void)in_sizes; (void)n_in; (void)out_size;

    const float* x         = (const float*)d_in[0];
    const float* y         = (const float*)d_in[1];
    const int*   adj_rows  = (const int*)d_in[2];
    const int*   adj_cols  = (const int*)d_in[3];
    const float* adj_vals  = (const float*)d_in[4];
    const int*   agg_rows  = (const int*)d_in[5];
    const float* agg_vals  = (const float*)d_in[6];
    const int*   perm      = (const int*)d_in[7];
    const float* mlp_W     = (const float*)d_in[8];
    const float* mlp_b     = (const float*)d_in[9];
    const float* bn_gamma  = (const float*)d_in[10];
    const float* bn_beta   = (const float*)d_in[11];
    const float* hg_W1     = (const float*)d_in[12];
    const float* hg_b1     = (const float*)d_in[13];
    const float* hg_W2     = (const float*)d_in[14];
    const float* hg_b2     = (const float*)d_in[15];
    const float* hg_prelu  = (const float*)d_in[16];
    const float* pred_W    = (const float*)d_in[17];
    const float* pred_b    = (const float*)d_in[18];
    const float* dgi_W     = (const float*)d_in[19];
    const float* dgi_b     = (const float*)d_in[20];
    const float* dgi_prelu = (const float*)d_in[21];

    float* out = (float*)d_out_v;
    float* xp  = out + 1;  // x_prime: (50000, 280), loss at out[0]

    float *h0, *z, *t, *zd, *s1, *s2, *agg, *stats, *scale, *shift, *cbuf, *acc;
    int* pcols;
    cudaGetSymbolAddress((void**)&h0,    g_h0);
    cudaGetSymbolAddress((void**)&z,     g_z);
    cudaGetSymbolAddress((void**)&t,     g_t);
    cudaGetSymbolAddress((void**)&zd,    g_zd);
    cudaGetSymbolAddress((void**)&s1,    g_s1);
    cudaGetSymbolAddress((void**)&s2,    g_s2);
    cudaGetSymbolAddress((void**)&agg,   g_agg);
    cudaGetSymbolAddress((void**)&stats, g_stats);
    cudaGetSymbolAddress((void**)&scale, g_scale);
    cudaGetSymbolAddress((void**)&shift, g_shift);
    cudaGetSymbolAddress((void**)&cbuf,  g_c);
    cudaGetSymbolAddress((void**)&acc,   g_acc);
    cudaGetSymbolAddress((void**)&pcols, g_pcols);

    cudaStream_t st = 0;
    const dim3 gH(cdiv(HIDD, 128), cdiv(NROWS, 128));   // N=256 tiles
    const dim3 gO(cdiv(OUTF, 128), cdiv(NROWS, 128));   // N=280 tiles

    // ---- MLP: leaky(x @ mlp_W + b, 0.1) ----
    sgemm_kernel<ACT_LEAKY><<<gH, 256, 0, st>>>(x, mlp_W, mlp_b, z, NROWS, HIDD, FIN, 0.1f, nullptr);

    // ---- BatchNorm (training stats) ----
    cudaMemsetAsync(stats, 0, 2 * HIDD * sizeof(float), st);
    bn_stats_kernel<<<256, 256, 0, st>>>(z, stats);
    bn_finalize_kernel<<<1, HIDD, 0, st>>>(stats, bn_gamma, bn_beta, scale, shift);
    bn_apply_kernel<<<cdiv(NROWS * HIDD, 256), 256, 0, st>>>(z, h0, scale, shift);

    // ---- HGNN layer 1 ----
    sgemm_kernel<ACT_NONE><<<gH, 256, 0, st>>>(h0, hg_W1, hg_b1, z, NROWS, HIDD, HIDD, 0.f, nullptr);
    cudaMemsetAsync(t, 0, (size_t)NROWS * HIDD * sizeof(float), st);
    spmm_kernel<HIDD><<<cdiv(NNZE * HIDD, 256), 256, 0, st>>>(adj_rows, adj_cols, adj_vals, z, t);
    act_prelu_kernel<<<cdiv(NROWS * HIDD, 256), 256, 0, st>>>(t, NROWS * HIDD, hg_prelu);

    // ---- HGNN layer 2 ----
    sgemm_kernel<ACT_NONE><<<gH, 256, 0, st>>>(t, hg_W2, hg_b2, z, NROWS, HIDD, HIDD, 0.f, nullptr);
    cudaMemsetAsync(t, 0, (size_t)NROWS * HIDD * sizeof(float), st);
    spmm_kernel<HIDD><<<cdiv(NNZE * HIDD, 256), 256, 0, st>>>(adj_rows, adj_cols, adj_vals, z, t);
    act_leaky_kernel<<<cdiv(NROWS * HIDD, 256), 256, 0, st>>>(t, NROWS * HIDD, 0.01f);

    // ---- prediction head: x_prime = leaky(h @ pred_W + b, 0.01) ----
    sgemm_kernel<ACT_LEAKY><<<gO, 256, 0, st>>>(t, pred_W, pred_b, xp, NROWS, OUTF, HIDD, 0.01f, nullptr);

    // ---- Xenium MSE: agg = segment_sum(agg_vals * x_prime) ----
    cudaMemsetAsync(agg, 0, (size_t)SROWS * OUTF * sizeof(float), st);
    cudaMemsetAsync(acc, 0, 4 * sizeof(float), st);
    agg_kernel<<<cdiv(NROWS * OUTF, 256), 256, 0, st>>>(agg_rows, agg_vals, xp, agg);
    mse_kernel<<<2048, 256, 0, st>>>(agg, y, acc);

    // ---- DGI: zd = h0 @ dgi_W + b (perm branch reuses zd via perm∘cols) ----
    sgemm_kernel<ACT_NONE><<<gO, 256, 0, st>>>(h0, dgi_W, dgi_b, zd, NROWS, OUTF, HIDD, 0.f, nullptr);
    permcols_kernel<<<cdiv(NNZE, 256), 256, 0, st>>>(adj_cols, perm, pcols);
    cudaMemsetAsync(s1, 0, (size_t)NROWS * OUTF * sizeof(float), st);
    cudaMemsetAsync(s2, 0, (size_t)NROWS * OUTF * sizeof(float), st);
    spmm_kernel<OUTF><<<cdiv(NNZE * OUTF, 256), 256, 0, st>>>(adj_rows, adj_cols, adj_vals, zd, s1);
    spmm_kernel<OUTF><<<cdiv(NNZE * OUTF, 256), 256, 0, st>>>(adj_rows, pcols, adj_vals, zd, s2);
    act_prelu_kernel<<<cdiv(NROWS * OUTF, 256), 256, 0, st>>>(s1, NROWS * OUTF, dgi_prelu);
    act_prelu_kernel<<<cdiv(NROWS * OUTF, 256), 256, 0, st>>>(s2, NROWS * OUTF, dgi_prelu);

    // ---- summary vector c, norm, cosine terms ----
    cudaMemsetAsync(cbuf, 0, OUTF * sizeof(float), st);
    colsum_kernel<<<256, 256, 0, st>>>(s1, cbuf);
    c_finalize_kernel<<<1, 512, 0, st>>>(cbuf, acc);
    cos_kernel<<<cdiv(NROWS, 8), 256, 0, st>>>(s1, s2, cbuf, acc);

    // ---- final loss ----
    final_kernel<<<1, 1, 0, st>>>(acc, out);
}

// round 5
// speedup vs baseline: 2.9484x; 2.8629x over previous
#include <cuda_runtime.h>
#include <cuda_bf16.h>
#include <math.h>
#include <stdint.h>

#define NROWS 50000
#define FIN   1024
#define HIDD  256
#define OUTF  280
#define SROWS 5000
#define NNZE  800000

enum { ACT_NONE = 0, ACT_LEAKY = 1, ACT_PRELU = 2 };

// ---- static device scratch ----
__device__ __align__(256) __nv_bfloat16 g_ah[(size_t)NROWS*FIN];
__device__ __align__(256) __nv_bfloat16 g_al[(size_t)NROWS*FIN];
__device__ __align__(256) __nv_bfloat16 g_h0h[(size_t)NROWS*HIDD];
__device__ __align__(256) __nv_bfloat16 g_h0l[(size_t)NROWS*HIDD];
__device__ __align__(256) __nv_bfloat16 g_th[(size_t)NROWS*HIDD];
__device__ __align__(256) __nv_bfloat16 g_tl[(size_t)NROWS*HIDD];
__device__ __align__(256) __nv_bfloat16 g_hh[(size_t)NROWS*HIDD];
__device__ __align__(256) __nv_bfloat16 g_hl[(size_t)NROWS*HIDD];
__device__ __align__(256) float g_z  [(size_t)NROWS*HIDD];
__device__ __align__(256) float g_zd [(size_t)NROWS*OUTF];
__device__ __align__(256) float g_s1 [(size_t)NROWS*OUTF];
__device__ __align__(256) float g_s2 [(size_t)NROWS*OUTF];
__device__ __align__(256) float g_agg[(size_t)SROWS*OUTF];
__device__ __align__(256) __nv_bfloat16 g_w[1073152];
__device__ __align__(256) float g_stats[2*HIDD];
__device__ __align__(256) float g_scale[HIDD];
__device__ __align__(256) float g_shift[HIDD];
__device__ __align__(256) float g_c[OUTF];
__device__ __align__(256) float g_acc[4];
__device__ __align__(256) int   g_rowptr[NROWS+1];
__device__ __align__(256) int   g_cnt[NROWS];
__device__ __align__(256) int   g_ecol[NNZE];
__device__ __align__(256) int   g_ecolp[NNZE];
__device__ __align__(256) float g_eval[NNZE];

#define OFF_MLP  0
#define SZ_MLP   (HIDD*FIN)
#define OFF_HG1  (OFF_MLP + 2*SZ_MLP)
#define SZ_HG    (HIDD*HIDD)
#define OFF_HG2  (OFF_HG1 + 2*SZ_HG)
#define OFF_PRED (OFF_HG2 + 2*SZ_HG)
#define SZ_PD    (OUTF*HIDD)
#define OFF_DGI  (OFF_PRED + 2*SZ_PD)

// ---- helpers ----
__device__ __forceinline__ uint32_t smem_u32(const void* p) {
    uint32_t a;
    asm("{ .reg .u64 t; cvta.to.shared.u64 t, %1; cvt.u32.u64 %0, t; }" : "=r"(a) : "l"(p));
    return a;
}
__device__ __forceinline__ void ldm4(uint32_t* r, uint32_t addr) {
    asm volatile("ldmatrix.sync.aligned.m8n8.x4.shared.b16 {%0,%1,%2,%3}, [%4];"
        : "=r"(r[0]), "=r"(r[1]), "=r"(r[2]), "=r"(r[3]) : "r"(addr));
}
__device__ __forceinline__ void mma_16816(float* d, const uint32_t* a, uint32_t b0, uint32_t b1) {
    asm volatile(
        "mma.sync.aligned.m16n8k16.row.col.f32.bf16.bf16.f32 "
        "{%0,%1,%2,%3}, {%4,%5,%6,%7}, {%8,%9}, {%0,%1,%2,%3};"
        : "+f"(d[0]), "+f"(d[1]), "+f"(d[2]), "+f"(d[3])
        : "r"(a[0]), "r"(a[1]), "r"(a[2]), "r"(a[3]), "r"(b0), "r"(b1));
}

// ---- mma.sync bf16 split GEMM: C[M,N] = (Ah+Al)@(Bh+Bl)^T + bias (+act) ----
// A: [M,K] bf16 hi/lo; B: [N,K] bf16 hi/lo. Per k-tile: AhBh + AlBh + AhBl.
// CTA 128x128, KT=32, 8 warps (2M x 4N), warp tile 64x32.
// smem per stage: Ah,Al,Bh,Bl each 128 rows x 32 cols padded to 40 (80B rows) = 10240B.
// NOTE: epilogue stores are SCALAR — C may be only 4-byte aligned (xp = out+1).
template<int ACT>
__global__ __launch_bounds__(256, 1)
void mma_gemm_kernel(const __nv_bfloat16* __restrict__ Ah, const __nv_bfloat16* __restrict__ Al,
                     const __nv_bfloat16* __restrict__ Bh, const __nv_bfloat16* __restrict__ Bl,
                     const float* __restrict__ bias, float* __restrict__ C,
                     int M, int N, int K, float slope)
{
    extern __shared__ char smem[];
    const uint32_t s0 = smem_u32(smem);
    const int tid  = threadIdx.x;
    const int warp = tid >> 5, lane = tid & 31;
    const int bm = blockIdx.y * 128, bn = blockIdx.x * 128;
    const int wm = (warp >> 2) * 64;
    const int wn = (warp & 3) * 32;

    float acc[4][4][4];
    #pragma unroll
    for (int i = 0; i < 4; i++)
        #pragma unroll
        for (int j = 0; j < 4; j++)
            #pragma unroll
            for (int q = 0; q < 4; q++) acc[i][j][q] = 0.f;

    const int T = K >> 5;  // KT = 32

    auto load_stage = [&](int t, int buf) {
        const uint32_t base = s0 + (uint32_t)buf * 40960u;
        const int k0 = t << 5;
        #pragma unroll
        for (int c = tid; c < 2048; c += 256) {
            int mat = c >> 9;           // 0 Ah, 1 Al, 2 Bh, 3 Bl
            int idx = c & 511;
            int row = idx >> 2, seg = idx & 3;
            uint32_t dst = base + (uint32_t)mat * 10240u + (uint32_t)(row * 80 + seg * 16);
            const __nv_bfloat16* P;
            int grow, lim;
            if (mat < 2) { P = mat ? Al : Ah; grow = bm + row; lim = M; }
            else         { P = (mat == 3) ? Bl : Bh; grow = bn + row; lim = N; }
            bool ok = grow < lim;
            const char* src = (const char*)(P + (size_t)(ok ? grow : 0) * K + k0) + seg * 16;
            int sz = ok ? 16 : 0;
            asm volatile("cp.async.cg.shared.global [%0], [%1], 16, %2;"
                         :: "r"(dst), "l"(src), "r"(sz));
        }
    };

    load_stage(0, 0);
    asm volatile("cp.async.commit_group;" ::: "memory");

    const int lrow = lane & 15;
    const int lkof = (lane >> 4) * 16;   // +8 k elements = 16 bytes

    for (int t = 0; t < T; t++) {
        if (t + 1 < T) {
            load_stage(t + 1, (t + 1) & 1);
            asm volatile("cp.async.commit_group;" ::: "memory");
            asm volatile("cp.async.wait_group 1;" ::: "memory");
        } else {
            asm volatile("cp.async.wait_group 0;" ::: "memory");
        }
        __syncthreads();

        const uint32_t base = s0 + (uint32_t)(t & 1) * 40960u;
        #pragma unroll
        for (int kk = 0; kk < 2; kk++) {
            const uint32_t koff = (uint32_t)(kk * 32 + lkof);
            uint32_t a_h[4][4], a_l[4][4];
            #pragma unroll
            for (int i = 0; i < 4; i++) {
                uint32_t r = (uint32_t)((wm + i * 16 + lrow) * 80) + koff;
                ldm4(a_h[i], base + r);
                ldm4(a_l[i], base + 10240u + r);
            }
            uint32_t b_h[2][4], b_l[2][4];
            #pragma unroll
            for (int j2 = 0; j2 < 2; j2++) {
                uint32_t r = (uint32_t)((wn + j2 * 16 + lrow) * 80) + koff;
                ldm4(b_h[j2], base + 20480u + r);
                ldm4(b_l[j2], base + 30720u + r);
            }
            #pragma unroll
            for (int i = 0; i < 4; i++) {
                #pragma unroll
                for (int j = 0; j < 4; j++) {
                    const int j2 = j >> 1, sel = j & 1;
                    mma_16816(acc[i][j], a_h[i], b_h[j2][sel], b_h[j2][sel + 2]);
                    mma_16816(acc[i][j], a_l[i], b_h[j2][sel], b_h[j2][sel + 2]);
                    mma_16816(acc[i][j], a_h[i], b_l[j2][sel], b_l[j2][sel + 2]);
                }
            }
        }
        __syncthreads();
    }

    // epilogue: scalar stores (C may be 4-byte aligned only)
    const int g = lane >> 2, tig = lane & 3;
    #pragma unroll
    for (int i = 0; i < 4; i++) {
        const int r0 = bm + wm + i * 16 + g;
        const int r1 = r0 + 8;
        #pragma unroll
        for (int j = 0; j < 4; j++) {
            const int col = bn + wn + j * 8 + tig * 2;
            #pragma unroll
            for (int e = 0; e < 2; e++) {
                const int cc = col + e;
                if (cc < N) {
                    float bb = bias[cc];
                    if (r0 < M) {
                        float v = acc[i][j][e] + bb;
                        if (ACT) v = (v >= 0.f) ? v : slope * v;
                        C[(size_t)r0 * N + cc] = v;
                    }
                    if (r1 < M) {
                        float v = acc[i][j][2 + e] + bb;
                        if (ACT) v = (v >= 0.f) ? v : slope * v;
                        C[(size_t)r1 * N + cc] = v;
                    }
                }
            }
        }
    }
}

// ---- bf16 hi/lo split helpers ----
__device__ __forceinline__ void split_bf16(float v, __nv_bfloat16& h, __nv_bfloat16& l) {
    h = __float2bfloat16(v);
    l = __float2bfloat16(v - __bfloat162float(h));
}
__global__ void split4_kernel(const float4* __restrict__ in, __nv_bfloat16* __restrict__ oh,
                              __nv_bfloat16* __restrict__ ol, int n4)
{
    int i = blockIdx.x * blockDim.x + threadIdx.x;
    if (i >= n4) return;
    float4 v = in[i];
    __nv_bfloat16 h0,h1,h2,h3,l0,l1,l2,l3;
    split_bf16(v.x,h0,l0); split_bf16(v.y,h1,l1); split_bf16(v.z,h2,l2); split_bf16(v.w,h3,l3);
    __nv_bfloat162* ph = reinterpret_cast<__nv_bfloat162*>(oh + (size_t)i*4);
    __nv_bfloat162* pl = reinterpret_cast<__nv_bfloat162*>(ol + (size_t)i*4);
    ph[0] = __nv_bfloat162(h0,h1); ph[1] = __nv_bfloat162(h2,h3);
    pl[0] = __nv_bfloat162(l0,l1); pl[1] = __nv_bfloat162(l2,l3);
}
__global__ void wtrans_kernel(const float* __restrict__ W, __nv_bfloat16* __restrict__ oh,
                              __nv_bfloat16* __restrict__ ol, int K, int N)
{
    int idx = blockIdx.x * blockDim.x + threadIdx.x;
    if (idx >= K * N) return;
    int k = idx / N, n = idx - k * N;
    __nv_bfloat16 h, l;
    split_bf16(W[idx], h, l);
    size_t o = (size_t)n * K + k;
    oh[o] = h; ol[o] = l;
}

// ---- BatchNorm ----
__global__ void bn_stats_kernel(const float* __restrict__ H, float* __restrict__ stats)
{
    const int col = threadIdx.x;
    const int rpb = (NROWS + gridDim.x - 1) / gridDim.x;
    const int r0 = blockIdx.x * rpb, r1 = min(NROWS, r0 + rpb);
    float s = 0.f, ss = 0.f;
    for (int r = r0; r < r1; r++) {
        float v = H[(size_t)r * HIDD + col];
        s += v; ss = fmaf(v, v, ss);
    }
    atomicAdd(&stats[col], s);
    atomicAdd(&stats[HIDD + col], ss);
}
__global__ void bn_finalize_kernel(const float* __restrict__ stats, const float* __restrict__ gamma,
                                   const float* __restrict__ beta, float* __restrict__ scale,
                                   float* __restrict__ shift)
{
    int c = threadIdx.x;
    float mu  = stats[c] * (1.0f / NROWS);
    float var = stats[HIDD + c] * (1.0f / NROWS) - mu * mu;
    float sc  = gamma[c] * rsqrtf(var + 1e-5f);
    scale[c] = sc;
    shift[c] = beta[c] - mu * sc;
}
__global__ void bn_apply_split_kernel(const float4* __restrict__ in, __nv_bfloat16* __restrict__ oh,
                                      __nv_bfloat16* __restrict__ ol, const float* __restrict__ scale,
                                      const float* __restrict__ shift)
{
    int i = blockIdx.x * blockDim.x + threadIdx.x;
    if (i >= NROWS * HIDD / 4) return;
    int c0 = (i * 4) & (HIDD - 1);
    float4 v = in[i];
    float a = fmaf(v.x, scale[c0], shift[c0]);
    float b = fmaf(v.y, scale[c0+1], shift[c0+1]);
    float c = fmaf(v.z, scale[c0+2], shift[c0+2]);
    float d = fmaf(v.w, scale[c0+3], shift[c0+3]);
    __nv_bfloat16 h0,h1,h2,h3,l0,l1,l2,l3;
    split_bf16(a,h0,l0); split_bf16(b,h1,l1); split_bf16(c,h2,l2); split_bf16(d,h3,l3);
    __nv_bfloat162* ph = reinterpret_cast<__nv_bfloat162*>(oh + (size_t)i*4);
    __nv_bfloat162* pl = reinterpret_cast<__nv_bfloat162*>(ol + (size_t)i*4);
    ph[0] = __nv_bfloat162(h0,h1); ph[1] = __nv_bfloat162(h2,h3);
    pl[0] = __nv_bfloat162(l0,l1); pl[1] = __nv_bfloat162(l2,l3);
}

// ---- CSR build ----
__global__ void hist_kernel(const int* __restrict__ rows, int* __restrict__ cnt)
{
    int e = blockIdx.x * blockDim.x + threadIdx.x;
    if (e < NNZE) atomicAdd(&cnt[rows[e]], 1);
}
__global__ void scan_kernel(const int* __restrict__ cnt, int* __restrict__ rowptr)
{
    __shared__ int sh[1024];
    __shared__ int carry;
    if (threadIdx.x == 0) carry = 0;
    __syncthreads();
    for (int base = 0; base < NROWS; base += 1024) {
        int i = base + threadIdx.x;
        int v = (i < NROWS) ? cnt[i] : 0;
        sh[threadIdx.x] = v;
        __syncthreads();
        #pragma unroll
        for (int off = 1; off < 1024; off <<= 1) {
            int t = (threadIdx.x >= off) ? sh[threadIdx.x - off] : 0;
            __syncthreads();
            sh[threadIdx.x] += t;
            __syncthreads();
        }
        if (i < NROWS) rowptr[i] = carry + sh[threadIdx.x] - v;
        int total = sh[1023];
        __syncthreads();
        if (threadIdx.x == 0) carry += total;
        __syncthreads();
    }
    if (threadIdx.x == 0) rowptr[NROWS] = carry;
}
__global__ void scatter_kernel(const int* __restrict__ rows, const int* __restrict__ cols,
                               const float* __restrict__ vals, const int* __restrict__ perm,
                               const int* __restrict__ rowptr, int* __restrict__ cnt2,
                               int* __restrict__ ecol, float* __restrict__ eval,
                               int* __restrict__ ecolp)
{
    int e = blockIdx.x * blockDim.x + threadIdx.x;
    if (e >= NNZE) return;
    int r = rows[e];
    int p = rowptr[r] + atomicAdd(&cnt2[r], 1);
    int c = cols[e];
    ecol[p] = c; eval[p] = vals[e]; ecolp[p] = perm[c];
}

// ---- CSR SpMM with fused activation (+optional bf16 split output) ----
template<int F, int ACT, bool BF16OUT>
__global__ void spmm_csr_kernel(const int* __restrict__ rowptr, const int* __restrict__ ecol,
                                const float* __restrict__ eval, const float* __restrict__ Z,
                                float* __restrict__ outf, __nv_bfloat16* __restrict__ oh,
                                __nv_bfloat16* __restrict__ ol, float slope,
                                const float* __restrict__ alpha_ptr)
{
    const int r = blockIdx.x;
    const int f = threadIdx.x;
    __shared__ int   scol[128];
    __shared__ float sval[128];
    float acc = 0.f;
    const int e0 = rowptr[r], e1 = rowptr[r + 1];
    for (int base = e0; base < e1; base += 128) {
        int cnt = min(128, e1 - base);
        __syncthreads();
        if (threadIdx.x < cnt) {
            scol[threadIdx.x] = ecol[base + threadIdx.x];
            sval[threadIdx.x] = eval[base + threadIdx.x];
        }
        __syncthreads();
        if (f < F) {
            #pragma unroll 4
            for (int j = 0; j < cnt; j++)
                acc = fmaf(sval[j], Z[(size_t)scol[j] * F + f], acc);
        }
    }
    if (f >= F) return;
    float a = (ACT == ACT_PRELU) ? *alpha_ptr : slope;
    float v = (ACT == ACT_NONE) ? acc : ((acc >= 0.f) ? acc : a * acc);
    size_t o = (size_t)r * F + f;
    if (BF16OUT) {
        __nv_bfloat16 h, l;
        split_bf16(v, h, l);
        oh[o] = h; ol[o] = l;
    } else {
        outf[o] = v;
    }
}

// ---- agg scatter + MSE ----
__global__ void agg_kernel(const int* __restrict__ arows, const float* __restrict__ avals,
                           const float* __restrict__ xp, float* __restrict__ agg)
{
    int idx = blockIdx.x * blockDim.x + threadIdx.x;
    if (idx < NROWS * OUTF) {
        int i = idx / OUTF;
        int f = idx - i * OUTF;
        atomicAdd(&agg[(size_t)arows[i] * OUTF + f], avals[i] * xp[idx]);
    }
}
__global__ void mse_kernel(const float* __restrict__ agg, const float* __restrict__ y,
                           float* __restrict__ acc)
{
    __shared__ float sh[256];
    float s = 0.f;
    for (int idx = blockIdx.x * blockDim.x + threadIdx.x; idx < SROWS * OUTF;
         idx += gridDim.x * blockDim.x) {
        float d = agg[idx] - y[idx];
        s = fmaf(d, d, s);
    }
    sh[threadIdx.x] = s;
    __syncthreads();
    for (int o = 128; o; o >>= 1) {
        if (threadIdx.x < o) sh[threadIdx.x] += sh[threadIdx.x + o];
        __syncthreads();
    }
    if (threadIdx.x == 0) atomicAdd(&acc[0], sh[0]);
}

// ---- DGI summary + cosine ----
__global__ void colsum_kernel(const float* __restrict__ H, float* __restrict__ sums)
{
    const int rpb = (NROWS + gridDim.x - 1) / gridDim.x;
    const int r0 = blockIdx.x * rpb, r1 = min(NROWS, r0 + rpb);
    for (int c = threadIdx.x; c < OUTF; c += blockDim.x) {
        float s = 0.f;
        for (int r = r0; r < r1; r++) s += H[(size_t)r * OUTF + c];
        atomicAdd(&sums[c], s);
    }
}
__global__ void c_finalize_kernel(float* __restrict__ c, float* __restrict__ acc)
{
    __shared__ float sh[512];
    int t = threadIdx.x;
    float v = 0.f;
    if (t < OUTF) {
        float m = c[t] * (1.0f / NROWS);
        c[t] = m;
        v = m * m;
    }
    sh[t] = v;
    __syncthreads();
    for (int o = 256; o; o >>= 1) {
        if (t < o) sh[t] += sh[t + o];
        __syncthreads();
    }
    if (t == 0) acc[3] = sqrtf(sh[0]);
}
__global__ void cos_kernel(const float* __restrict__ h1, const float* __restrict__ h2,
                           const float* __restrict__ c, float* __restrict__ acc)
{
    const int warp = threadIdx.x >> 5, lane = threadIdx.x & 31;
    const int row = blockIdx.x * 8 + warp;
    float t1 = 0.f, t2 = 0.f;
    if (row < NROWS) {
        float d1 = 0.f, n1 = 0.f, d2 = 0.f, n2 = 0.f;
        const float* r1 = h1 + (size_t)row * OUTF;
        const float* r2 = h2 + (size_t)row * OUTF;
        for (int f = lane; f < OUTF; f += 32) {
            float cf = c[f], v1 = r1[f], v2 = r2[f];
            d1 = fmaf(v1, cf, d1); n1 = fmaf(v1, v1, n1);
            d2 = fmaf(v2, cf, d2); n2 = fmaf(v2, v2, n2);
        }
        #pragma unroll
        for (int o = 16; o; o >>= 1) {
            d1 += __shfl_down_sync(~0u, d1, o); n1 += __shfl_down_sync(~0u, n1, o);
            d2 += __shfl_down_sync(~0u, d2, o); n2 += __shfl_down_sync(~0u, n2, o);
        }
        if (lane == 0) {
            float cn = acc[3];
            t1 = 1.f - d1 / fmaxf(sqrtf(n1) * cn, 1e-8f);
            t2 = fmaxf(d2 / fmaxf(sqrtf(n2) * cn, 1e-8f), 0.f);
        }
    }
    __shared__ float sh1[8], sh2[8];
    if (lane == 0) { sh1[warp] = t1; sh2[warp] = t2; }
    __syncthreads();
    if (threadIdx.x == 0) {
        float a = 0.f, b = 0.f;
        #pragma unroll
        for (int w = 0; w < 8; w++) { a += sh1[w]; b += sh2[w]; }
        atomicAdd(&acc[1], a);
        atomicAdd(&acc[2], b);
    }
}
__global__ void final_kernel(const float* __restrict__ acc, float* __restrict__ out)
{
    out[0] = acc[0] * (1.0f / (SROWS * OUTF)) + acc[1] * (1.0f / NROWS) + acc[2] * (1.0f / NROWS);
}

// ---- host ----
static inline int cdiv(int a, int b) { return (a + b - 1) / b; }

extern "C" void kernel_launch(void* const* d_in, const int* in_sizes, int n_in,
                              void* d_out_v, int out_size)
{
    (void)in_sizes; (void)n_in; (void)out_size;
    const float* x        = (const float*)d_in[0];
    const float* y        = (const float*)d_in[1];
    const int*   adj_rows = (const int*)d_in[2];
    const int*   adj_cols = (const int*)d_in[3];
    const float* adj_vals = (const float*)d_in[4];
    const int*   agg_rows = (const int*)d_in[5];
    const float* agg_vals = (const float*)d_in[6];
    const int*   perm     = (const int*)d_in[7];
    const float* mlp_W = (const float*)d_in[8],  *mlp_b = (const float*)d_in[9];
    const float* bn_gamma = (const float*)d_in[10], *bn_beta = (const float*)d_in[11];
    const float* hg_W1 = (const float*)d_in[12], *hg_b1 = (const float*)d_in[13];
    const float* hg_W2 = (const float*)d_in[14], *hg_b2 = (const float*)d_in[15];
    const float* hg_prelu = (const float*)d_in[16];
    const float* pred_W = (const float*)d_in[17], *pred_b = (const float*)d_in[18];
    const float* dgi_W = (const float*)d_in[19],  *dgi_b = (const float*)d_in[20];
    const float* dgi_prelu = (const float*)d_in[21];

    float* out = (float*)d_out_v;
    float* xp  = out + 1;

    __nv_bfloat16 *ah,*al,*h0h,*h0l,*th,*tl,*hh,*hl,*w;
    float *z,*zd,*s1,*s2,*agg,*stats,*scale,*shift,*cbuf,*acc,*eval;
    int *rowptr,*cnt,*ecol,*ecolp;
    cudaGetSymbolAddress((void**)&ah, g_ah);   cudaGetSymbolAddress((void**)&al, g_al);
    cudaGetSymbolAddress((void**)&h0h, g_h0h); cudaGetSymbolAddress((void**)&h0l, g_h0l);
    cudaGetSymbolAddress((void**)&th, g_th);   cudaGetSymbolAddress((void**)&tl, g_tl);
    cudaGetSymbolAddress((void**)&hh, g_hh);   cudaGetSymbolAddress((void**)&hl, g_hl);
    cudaGetSymbolAddress((void**)&z, g_z);     cudaGetSymbolAddress((void**)&zd, g_zd);
    cudaGetSymbolAddress((void**)&s1, g_s1);   cudaGetSymbolAddress((void**)&s2, g_s2);
    cudaGetSymbolAddress((void**)&agg, g_agg); cudaGetSymbolAddress((void**)&w, g_w);
    cudaGetSymbolAddress((void**)&stats, g_stats); cudaGetSymbolAddress((void**)&scale, g_scale);
    cudaGetSymbolAddress((void**)&shift, g_shift); cudaGetSymbolAddress((void**)&cbuf, g_c);
    cudaGetSymbolAddress((void**)&acc, g_acc);
    cudaGetSymbolAddress((void**)&rowptr, g_rowptr); cudaGetSymbolAddress((void**)&cnt, g_cnt);
    cudaGetSymbolAddress((void**)&ecol, g_ecol);     cudaGetSymbolAddress((void**)&ecolp, g_ecolp);
    cudaGetSymbolAddress((void**)&eval, g_eval);

    cudaStream_t st = 0;
    const int SMEM = 81920;  // 2 stages x 40960B
    cudaFuncSetAttribute(mma_gemm_kernel<ACT_NONE>, cudaFuncAttributeMaxDynamicSharedMemorySize, SMEM);
    cudaFuncSetAttribute(mma_gemm_kernel<ACT_LEAKY>, cudaFuncAttributeMaxDynamicSharedMemorySize, SMEM);
    const int MT = cdiv(NROWS, 128);                 // 391
    const dim3 gH(cdiv(HIDD, 128), MT);              // 2 x 391
    const dim3 gO(cdiv(OUTF, 128), MT);              // 3 x 391

    // input splits + weight transposes + CSR build
    split4_kernel<<<cdiv(NROWS * FIN / 4, 256), 256, 0, st>>>((const float4*)x, ah, al, NROWS * FIN / 4);
    wtrans_kernel<<<cdiv(FIN * HIDD, 256), 256, 0, st>>>(mlp_W, w + OFF_MLP, w + OFF_MLP + SZ_MLP, FIN, HIDD);
    wtrans_kernel<<<cdiv(HIDD * HIDD, 256), 256, 0, st>>>(hg_W1, w + OFF_HG1, w + OFF_HG1 + SZ_HG, HIDD, HIDD);
    wtrans_kernel<<<cdiv(HIDD * HIDD, 256), 256, 0, st>>>(hg_W2, w + OFF_HG2, w + OFF_HG2 + SZ_HG, HIDD, HIDD);
    wtrans_kernel<<<cdiv(HIDD * OUTF, 256), 256, 0, st>>>(pred_W, w + OFF_PRED, w + OFF_PRED + SZ_PD, HIDD, OUTF);
    wtrans_kernel<<<cdiv(HIDD * OUTF, 256), 256, 0, st>>>(dgi_W, w + OFF_DGI, w + OFF_DGI + SZ_PD, HIDD, OUTF);
    cudaMemsetAsync(cnt, 0, NROWS * sizeof(int), st);
    hist_kernel<<<cdiv(NNZE, 256), 256, 0, st>>>(adj_rows, cnt);
    scan_kernel<<<1, 1024, 0, st>>>(cnt, rowptr);
    cudaMemsetAsync(cnt, 0, NROWS * sizeof(int), st);
    scatter_kernel<<<cdiv(NNZE, 256), 256, 0, st>>>(adj_rows, adj_cols, adj_vals, perm, rowptr, cnt, ecol, eval, ecolp);

    // MLP GEMM + BN
    mma_gemm_kernel<ACT_LEAKY><<<gH, 256, SMEM, st>>>(ah, al, w + OFF_MLP, w + OFF_MLP + SZ_MLP, mlp_b, z, NROWS, HIDD, FIN, 0.1f);
    cudaMemsetAsync(stats, 0, 2 * HIDD * sizeof(float), st);
    bn_stats_kernel<<<256, 256, 0, st>>>(z, stats);
    bn_finalize_kernel<<<1, HIDD, 0, st>>>(stats, bn_gamma, bn_beta, scale, shift);
    bn_apply_split_kernel<<<cdiv(NROWS * HIDD / 4, 256), 256, 0, st>>>((const float4*)z, h0h, h0l, scale, shift);

    // HGNN layer 1
    mma_gemm_kernel<ACT_NONE><<<gH, 256, SMEM, st>>>(h0h, h0l, w + OFF_HG1, w + OFF_HG1 + SZ_HG, hg_b1, z, NROWS, HIDD, HIDD, 0.f);
    spmm_csr_kernel<HIDD, ACT_PRELU, true><<<NROWS, 256, 0, st>>>(rowptr, ecol, eval, z, nullptr, th, tl, 0.f, hg_prelu);
    // HGNN layer 2
    mma_gemm_kernel<ACT_NONE><<<gH, 256, SMEM, st>>>(th, tl, w + OFF_HG2, w + OFF_HG2 + SZ_HG, hg_b2, z, NROWS, HIDD, HIDD, 0.f);
    spmm_csr_kernel<HIDD, ACT_LEAKY, true><<<NROWS, 256, 0, st>>>(rowptr, ecol, eval, z, nullptr, hh, hl, 0.01f, nullptr);

    // prediction head
    mma_gemm_kernel<ACT_LEAKY><<<gO, 256, SMEM, st>>>(hh, hl, w + OFF_PRED, w + OFF_PRED + SZ_PD, pred_b, xp, NROWS, OUTF, HIDD, 0.01f);

    // Xenium MSE
    cudaMemsetAsync(agg, 0, (size_t)SROWS * OUTF * sizeof(float), st);
    cudaMemsetAsync(acc, 0, 4 * sizeof(float), st);
    agg_kernel<<<cdiv(NROWS * OUTF, 256), 256, 0, st>>>(agg_rows, agg_vals, xp, agg);
    mse_kernel<<<2048, 256, 0, st>>>(agg, y, acc);

    // DGI
    mma_gemm_kernel<ACT_NONE><<<gO, 256, SMEM, st>>>(h0h, h0l, w + OFF_DGI, w + OFF_DGI + SZ_PD, dgi_b, zd, NROWS, OUTF, HIDD, 0.f);
    spmm_csr_kernel<OUTF, ACT_PRELU, false><<<NROWS, 288, 0, st>>>(rowptr, ecol, eval, zd, s1, nullptr, nullptr, 0.f, dgi_prelu);
    spmm_csr_kernel<OUTF, ACT_PRELU, false><<<NROWS, 288, 0, st>>>(rowptr, ecolp, eval, zd, s2, nullptr, nullptr, 0.f, dgi_prelu);

    cudaMemsetAsync(cbuf, 0, OUTF * sizeof(float), st);
    colsum_kernel<<<256, 256, 0, st>>>(s1, cbuf);
    c_finalize_kernel<<<1, 512, 0, st>>>(cbuf, acc);
    cos_kernel<<<cdiv(NROWS, 8), 256, 0, st>>>(s1, s2, cbuf, acc);
    final_kernel<<<1, 1, 0, st>>>(acc, out);
}

// round 6
// speedup vs baseline: 3.1869x; 1.0809x over previous
#include <cuda_runtime.h>
#include <cuda_bf16.h>
#include <math.h>
#include <stdint.h>

#define NROWS 50000
#define FIN   1024
#define HIDD  256
#define OUTF  280
#define SROWS 5000
#define NNZE  800000

enum { ACT_NONE = 0, ACT_LEAKY = 1, ACT_PRELU = 2 };

// ---- static device scratch ----
__device__ __align__(256) __nv_bfloat16 g_ah[(size_t)NROWS*FIN];
__device__ __align__(256) __nv_bfloat16 g_al[(size_t)NROWS*FIN];
__device__ __align__(256) __nv_bfloat16 g_h0h[(size_t)NROWS*HIDD];
__device__ __align__(256) __nv_bfloat16 g_h0l[(size_t)NROWS*HIDD];
__device__ __align__(256) __nv_bfloat16 g_th[(size_t)NROWS*HIDD];
__device__ __align__(256) __nv_bfloat16 g_tl[(size_t)NROWS*HIDD];
__device__ __align__(256) __nv_bfloat16 g_hh[(size_t)NROWS*HIDD];
__device__ __align__(256) __nv_bfloat16 g_hl[(size_t)NROWS*HIDD];
__device__ __align__(256) float g_z  [(size_t)NROWS*HIDD];
__device__ __align__(256) float g_zd [(size_t)NROWS*OUTF];
__device__ __align__(256) float g_s1 [(size_t)NROWS*OUTF];
__device__ __align__(256) float g_s2 [(size_t)NROWS*OUTF];
__device__ __align__(256) float g_agg[(size_t)SROWS*OUTF];
__device__ __align__(256) __nv_bfloat16 g_w[1073152];
__device__ __align__(256) float g_stats[2*HIDD];
__device__ __align__(256) float g_scale[HIDD];
__device__ __align__(256) float g_shift[HIDD];
__device__ __align__(256) float g_c[OUTF];
__device__ __align__(256) float g_acc[4];
__device__ __align__(256) int   g_rowptr[NROWS+1];
__device__ __align__(256) int   g_cnt[NROWS];
__device__ __align__(256) int   g_ecol[NNZE];
__device__ __align__(256) int   g_ecolp[NNZE];
__device__ __align__(256) float g_eval[NNZE];

#define OFF_MLP  0
#define SZ_MLP   (HIDD*FIN)
#define OFF_HG1  (OFF_MLP + 2*SZ_MLP)
#define SZ_HG    (HIDD*HIDD)
#define OFF_HG2  (OFF_HG1 + 2*SZ_HG)
#define OFF_PRED (OFF_HG2 + 2*SZ_HG)
#define SZ_PD    (OUTF*HIDD)
#define OFF_DGI  (OFF_PRED + 2*SZ_PD)

// ---- helpers ----
__device__ __forceinline__ uint32_t smem_u32(const void* p) {
    uint32_t a;
    asm("{ .reg .u64 t; cvta.to.shared.u64 t, %1; cvt.u32.u64 %0, t; }" : "=r"(a) : "l"(p));
    return a;
}
__device__ __forceinline__ void ldm4(uint32_t* r, uint32_t addr) {
    asm volatile("ldmatrix.sync.aligned.m8n8.x4.shared.b16 {%0,%1,%2,%3}, [%4];"
        : "=r"(r[0]), "=r"(r[1]), "=r"(r[2]), "=r"(r[3]) : "r"(addr));
}
__device__ __forceinline__ void mma_16816(float* d, const uint32_t* a, uint32_t b0, uint32_t b1) {
    asm volatile(
        "mma.sync.aligned.m16n8k16.row.col.f32.bf16.bf16.f32 "
        "{%0,%1,%2,%3}, {%4,%5,%6,%7}, {%8,%9}, {%0,%1,%2,%3};"
        : "+f"(d[0]), "+f"(d[1]), "+f"(d[2]), "+f"(d[3])
        : "r"(a[0]), "r"(a[1]), "r"(a[2]), "r"(a[3]), "r"(b0), "r"(b1));
}

// ---- mma.sync bf16 split GEMM: C[M,N] = (Ah+Al)@(Bh+Bl)^T + bias (+act) ----
// 3-stage cp.async pipeline, one __syncthreads per k-tile.
// CTA 128x128, KT=32, 8 warps (2M x 4N), warp tile 64x32.
// smem per stage: Ah,Al,Bh,Bl each 128 rows x 80B = 10240B; 3 stages = 122880B.
// Epilogue stores are SCALAR (C may be only 4-byte aligned: xp = out+1).
template<int ACT>
__global__ __launch_bounds__(256, 1)
void mma_gemm_kernel(const __nv_bfloat16* __restrict__ Ah, const __nv_bfloat16* __restrict__ Al,
                     const __nv_bfloat16* __restrict__ Bh, const __nv_bfloat16* __restrict__ Bl,
                     const float* __restrict__ bias, float* __restrict__ C,
                     int M, int N, int K, float slope)
{
    extern __shared__ char smem[];
    const uint32_t s0 = smem_u32(smem);
    const int tid  = threadIdx.x;
    const int warp = tid >> 5, lane = tid & 31;
    const int bm = blockIdx.y * 128, bn = blockIdx.x * 128;
    const int wm = (warp >> 2) * 64;
    const int wn = (warp & 3) * 32;

    float acc[4][4][4];
    #pragma unroll
    for (int i = 0; i < 4; i++)
        #pragma unroll
        for (int j = 0; j < 4; j++)
            #pragma unroll
            for (int q = 0; q < 4; q++) acc[i][j][q] = 0.f;

    const int T = K >> 5;  // KT = 32

    auto load_stage = [&](int t, int buf) {
        const uint32_t base = s0 + (uint32_t)buf * 40960u;
        const int k0 = t << 5;
        #pragma unroll
        for (int c = tid; c < 2048; c += 256) {
            int mat = c >> 9;           // 0 Ah, 1 Al, 2 Bh, 3 Bl
            int idx = c & 511;
            int row = idx >> 2, seg = idx & 3;
            uint32_t dst = base + (uint32_t)mat * 10240u + (uint32_t)(row * 80 + seg * 16);
            const __nv_bfloat16* P;
            int grow, lim;
            if (mat < 2) { P = mat ? Al : Ah; grow = bm + row; lim = M; }
            else         { P = (mat == 3) ? Bl : Bh; grow = bn + row; lim = N; }
            bool ok = grow < lim;
            const char* src = (const char*)(P + (size_t)(ok ? grow : 0) * K + k0) + seg * 16;
            int sz = ok ? 16 : 0;
            asm volatile("cp.async.cg.shared.global [%0], [%1], 16, %2;"
                         :: "r"(dst), "l"(src), "r"(sz));
        }
    };

    load_stage(0, 0);
    asm volatile("cp.async.commit_group;" ::: "memory");
    if (T > 1) load_stage(1, 1);
    asm volatile("cp.async.commit_group;" ::: "memory");

    const int lrow = lane & 15;
    const int lkof = (lane >> 4) * 16;   // +8 k elements = 16 bytes

    int buf = 0, nbuf;
    for (int t = 0; t < T; t++) {
        if (t + 1 < T) { asm volatile("cp.async.wait_group 1;" ::: "memory"); }
        else           { asm volatile("cp.async.wait_group 0;" ::: "memory"); }
        __syncthreads();
        if (t + 2 < T) {
            nbuf = buf + 2; if (nbuf >= 3) nbuf -= 3;
            load_stage(t + 2, nbuf);
            asm volatile("cp.async.commit_group;" ::: "memory");
        }

        const uint32_t base = s0 + (uint32_t)buf * 40960u;
        #pragma unroll
        for (int kk = 0; kk < 2; kk++) {
            const uint32_t koff = (uint32_t)(kk * 32 + lkof);
            uint32_t a_h[4][4], a_l[4][4];
            #pragma unroll
            for (int i = 0; i < 4; i++) {
                uint32_t r = (uint32_t)((wm + i * 16 + lrow) * 80) + koff;
                ldm4(a_h[i], base + r);
                ldm4(a_l[i], base + 10240u + r);
            }
            uint32_t b_h[2][4], b_l[2][4];
            #pragma unroll
            for (int j2 = 0; j2 < 2; j2++) {
                uint32_t r = (uint32_t)((wn + j2 * 16 + lrow) * 80) + koff;
                ldm4(b_h[j2], base + 20480u + r);
                ldm4(b_l[j2], base + 30720u + r);
            }
            #pragma unroll
            for (int i = 0; i < 4; i++) {
                #pragma unroll
                for (int j = 0; j < 4; j++) {
                    const int j2 = j >> 1, sel = j & 1;
                    mma_16816(acc[i][j], a_h[i], b_h[j2][sel], b_h[j2][sel + 2]);
                    mma_16816(acc[i][j], a_l[i], b_h[j2][sel], b_h[j2][sel + 2]);
                    mma_16816(acc[i][j], a_h[i], b_l[j2][sel], b_l[j2][sel + 2]);
                }
            }
        }
        buf++; if (buf >= 3) buf = 0;
    }

    // epilogue: scalar stores (C may be 4-byte aligned only)
    const int g = lane >> 2, tig = lane & 3;
    #pragma unroll
    for (int i = 0; i < 4; i++) {
        const int r0 = bm + wm + i * 16 + g;
        const int r1 = r0 + 8;
        #pragma unroll
        for (int j = 0; j < 4; j++) {
            const int col = bn + wn + j * 8 + tig * 2;
            #pragma unroll
            for (int e = 0; e < 2; e++) {
                const int cc = col + e;
                if (cc < N) {
                    float bb = bias[cc];
                    if (r0 < M) {
                        float v = acc[i][j][e] + bb;
                        if (ACT) v = (v >= 0.f) ? v : slope * v;
                        C[(size_t)r0 * N + cc] = v;
                    }
                    if (r1 < M) {
                        float v = acc[i][j][2 + e] + bb;
                        if (ACT) v = (v >= 0.f) ? v : slope * v;
                        C[(size_t)r1 * N + cc] = v;
                    }
                }
            }
        }
    }
}

// ---- bf16 hi/lo split helpers ----
__device__ __forceinline__ void split_bf16(float v, __nv_bfloat16& h, __nv_bfloat16& l) {
    h = __float2bfloat16(v);
    l = __float2bfloat16(v - __bfloat162float(h));
}
__global__ void split4_kernel(const float4* __restrict__ in, __nv_bfloat16* __restrict__ oh,
                              __nv_bfloat16* __restrict__ ol, int n4)
{
    int i = blockIdx.x * blockDim.x + threadIdx.x;
    if (i >= n4) return;
    float4 v = in[i];
    __nv_bfloat16 h0,h1,h2,h3,l0,l1,l2,l3;
    split_bf16(v.x,h0,l0); split_bf16(v.y,h1,l1); split_bf16(v.z,h2,l2); split_bf16(v.w,h3,l3);
    __nv_bfloat162* ph = reinterpret_cast<__nv_bfloat162*>(oh + (size_t)i*4);
    __nv_bfloat162* pl = reinterpret_cast<__nv_bfloat162*>(ol + (size_t)i*4);
    ph[0] = __nv_bfloat162(h0,h1); ph[1] = __nv_bfloat162(h2,h3);
    pl[0] = __nv_bfloat162(l0,l1); pl[1] = __nv_bfloat162(l2,l3);
}
__global__ void wtrans_kernel(const float* __restrict__ W, __nv_bfloat16* __restrict__ oh,
                              __nv_bfloat16* __restrict__ ol, int K, int N)
{
    int idx = blockIdx.x * blockDim.x + threadIdx.x;
    if (idx >= K * N) return;
    int k = idx / N, n = idx - k * N;
    __nv_bfloat16 h, l;
    split_bf16(W[idx], h, l);
    size_t o = (size_t)n * K + k;
    oh[o] = h; ol[o] = l;
}

// ---- BatchNorm ----
__global__ void bn_stats_kernel(const float* __restrict__ H, float* __restrict__ stats)
{
    const int col = threadIdx.x;
    const int rpb = (NROWS + gridDim.x - 1) / gridDim.x;
    const int r0 = blockIdx.x * rpb, r1 = min(NROWS, r0 + rpb);
    float s = 0.f, ss = 0.f;
    for (int r = r0; r < r1; r++) {
        float v = H[(size_t)r * HIDD + col];
        s += v; ss = fmaf(v, v, ss);
    }
    atomicAdd(&stats[col], s);
    atomicAdd(&stats[HIDD + col], ss);
}
__global__ void bn_finalize_kernel(const float* __restrict__ stats, const float* __restrict__ gamma,
                                   const float* __restrict__ beta, float* __restrict__ scale,
                                   float* __restrict__ shift)
{
    int c = threadIdx.x;
    float mu  = stats[c] * (1.0f / NROWS);
    float var = stats[HIDD + c] * (1.0f / NROWS) - mu * mu;
    float sc  = gamma[c] * rsqrtf(var + 1e-5f);
    scale[c] = sc;
    shift[c] = beta[c] - mu * sc;
}
__global__ void bn_apply_split_kernel(const float4* __restrict__ in, __nv_bfloat16* __restrict__ oh,
                                      __nv_bfloat16* __restrict__ ol, const float* __restrict__ scale,
                                      const float* __restrict__ shift)
{
    int i = blockIdx.x * blockDim.x + threadIdx.x;
    if (i >= NROWS * HIDD / 4) return;
    int c0 = (i * 4) & (HIDD - 1);
    float4 v = in[i];
    float a = fmaf(v.x, scale[c0], shift[c0]);
    float b = fmaf(v.y, scale[c0+1], shift[c0+1]);
    float c = fmaf(v.z, scale[c0+2], shift[c0+2]);
    float d = fmaf(v.w, scale[c0+3], shift[c0+3]);
    __nv_bfloat16 h0,h1,h2,h3,l0,l1,l2,l3;
    split_bf16(a,h0,l0); split_bf16(b,h1,l1); split_bf16(c,h2,l2); split_bf16(d,h3,l3);
    __nv_bfloat162* ph = reinterpret_cast<__nv_bfloat162*>(oh + (size_t)i*4);
    __nv_bfloat162* pl = reinterpret_cast<__nv_bfloat162*>(ol + (size_t)i*4);
    ph[0] = __nv_bfloat162(h0,h1); ph[1] = __nv_bfloat162(h2,h3);
    pl[0] = __nv_bfloat162(l0,l1); pl[1] = __nv_bfloat162(l2,l3);
}

// ---- CSR build ----
__global__ void hist_kernel(const int* __restrict__ rows, int* __restrict__ cnt)
{
    int e = blockIdx.x * blockDim.x + threadIdx.x;
    if (e < NNZE) atomicAdd(&cnt[rows[e]], 1);
}
__global__ void scan_kernel(const int* __restrict__ cnt, int* __restrict__ rowptr)
{
    __shared__ int sh[1024];
    __shared__ int carry;
    if (threadIdx.x == 0) carry = 0;
    __syncthreads();
    for (int base = 0; base < NROWS; base += 1024) {
        int i = base + threadIdx.x;
        int v = (i < NROWS) ? cnt[i] : 0;
        sh[threadIdx.x] = v;
        __syncthreads();
        #pragma unroll
        for (int off = 1; off < 1024; off <<= 1) {
            int t = (threadIdx.x >= off) ? sh[threadIdx.x - off] : 0;
            __syncthreads();
            sh[threadIdx.x] += t;
            __syncthreads();
        }
        if (i < NROWS) rowptr[i] = carry + sh[threadIdx.x] - v;
        int total = sh[1023];
        __syncthreads();
        if (threadIdx.x == 0) carry += total;
        __syncthreads();
    }
    if (threadIdx.x == 0) rowptr[NROWS] = carry;
}
__global__ void scatter_kernel(const int* __restrict__ rows, const int* __restrict__ cols,
                               const float* __restrict__ vals, const int* __restrict__ perm,
                               const int* __restrict__ rowptr, int* __restrict__ cnt2,
                               int* __restrict__ ecol, float* __restrict__ eval,
                               int* __restrict__ ecolp)
{
    int e = blockIdx.x * blockDim.x + threadIdx.x;
    if (e >= NNZE) return;
    int r = rows[e];
    int p = rowptr[r] + atomicAdd(&cnt2[r], 1);
    int c = cols[e];
    ecol[p] = c; eval[p] = vals[e]; ecolp[p] = perm[c];
}

// ---- CSR SpMM with fused activation (+optional bf16 split output) ----
template<int F, int ACT, bool BF16OUT>
__global__ void spmm_csr_kernel(const int* __restrict__ rowptr, const int* __restrict__ ecol,
                                const float* __restrict__ eval, const float* __restrict__ Z,
                                float* __restrict__ outf, __nv_bfloat16* __restrict__ oh,
                                __nv_bfloat16* __restrict__ ol, float slope,
                                const float* __restrict__ alpha_ptr)
{
    const int r = blockIdx.x;
    const int f = threadIdx.x;
    __shared__ int   scol[128];
    __shared__ float sval[128];
    float acc = 0.f;
    const int e0 = rowptr[r], e1 = rowptr[r + 1];
    for (int base = e0; base < e1; base += 128) {
        int cnt = min(128, e1 - base);
        __syncthreads();
        if (threadIdx.x < cnt) {
            scol[threadIdx.x] = ecol[base + threadIdx.x];
            sval[threadIdx.x] = eval[base + threadIdx.x];
        }
        __syncthreads();
        if (f < F) {
            #pragma unroll 4
            for (int j = 0; j < cnt; j++)
                acc = fmaf(sval[j], Z[(size_t)scol[j] * F + f], acc);
        }
    }
    if (f >= F) return;
    float a = (ACT == ACT_PRELU) ? *alpha_ptr : slope;
    float v = (ACT == ACT_NONE) ? acc : ((acc >= 0.f) ? acc : a * acc);
    size_t o = (size_t)r * F + f;
    if (BF16OUT) {
        __nv_bfloat16 h, l;
        split_bf16(v, h, l);
        oh[o] = h; ol[o] = l;
    } else {
        outf[o] = v;
    }
}

// ---- agg scatter + MSE ----
__global__ void agg_kernel(const int* __restrict__ arows, const float* __restrict__ avals,
                           const float* __restrict__ xp, float* __restrict__ agg)
{
    int idx = blockIdx.x * blockDim.x + threadIdx.x;
    if (idx < NROWS * OUTF) {
        int i = idx / OUTF;
        int f = idx - i * OUTF;
        atomicAdd(&agg[(size_t)arows[i] * OUTF + f], avals[i] * xp[idx]);
    }
}
__global__ void mse_kernel(const float* __restrict__ agg, const float* __restrict__ y,
                           float* __restrict__ acc)
{
    __shared__ float sh[256];
    float s = 0.f;
    for (int idx = blockIdx.x * blockDim.x + threadIdx.x; idx < SROWS * OUTF;
         idx += gridDim.x * blockDim.x) {
        float d = agg[idx] - y[idx];
        s = fmaf(d, d, s);
    }
    sh[threadIdx.x] = s;
    __syncthreads();
    for (int o = 128; o; o >>= 1) {
        if (threadIdx.x < o) sh[threadIdx.x] += sh[threadIdx.x + o];
        __syncthreads();
    }
    if (threadIdx.x == 0) atomicAdd(&acc[0], sh[0]);
}

// ---- DGI summary + cosine ----
__global__ void colsum_kernel(const float* __restrict__ H, float* __restrict__ sums)
{
    const int rpb = (NROWS + gridDim.x - 1) / gridDim.x;
    const int r0 = blockIdx.x * rpb, r1 = min(NROWS, r0 + rpb);
    for (int c = threadIdx.x; c < OUTF; c += blockDim.x) {
        float s = 0.f;
        for (int r = r0; r < r1; r++) s += H[(size_t)r * OUTF + c];
        atomicAdd(&sums[c], s);
    }
}
__global__ void c_finalize_kernel(float* __restrict__ c, float* __restrict__ acc)
{
    __shared__ float sh[512];
    int t = threadIdx.x;
    float v = 0.f;
    if (t < OUTF) {
        float m = c[t] * (1.0f / NROWS);
        c[t] = m;
        v = m * m;
    }
    sh[t] = v;
    __syncthreads();
    for (int o = 256; o; o >>= 1) {
        if (t < o) sh[t] += sh[t + o];
        __syncthreads();
    }
    if (t == 0) acc[3] = sqrtf(sh[0]);
}
__global__ void cos_kernel(const float* __restrict__ h1, const float* __restrict__ h2,
                           const float* __restrict__ c, float* __restrict__ acc)
{
    const int warp = threadIdx.x >> 5, lane = threadIdx.x & 31;
    const int row = blockIdx.x * 8 + warp;
    float t1 = 0.f, t2 = 0.f;
    if (row < NROWS) {
        float d1 = 0.f, n1 = 0.f, d2 = 0.f, n2 = 0.f;
        const float* r1 = h1 + (size_t)row * OUTF;
        const float* r2 = h2 + (size_t)row * OUTF;
        for (int f = lane; f < OUTF; f += 32) {
            float cf = c[f], v1 = r1[f], v2 = r2[f];
            d1 = fmaf(v1, cf, d1); n1 = fmaf(v1, v1, n1);
            d2 = fmaf(v2, cf, d2); n2 = fmaf(v2, v2, n2);
        }
        #pragma unroll
        for (int o = 16; o; o >>= 1) {
            d1 += __shfl_down_sync(~0u, d1, o); n1 += __shfl_down_sync(~0u, n1, o);
            d2 += __shfl_down_sync(~0u, d2, o); n2 += __shfl_down_sync(~0u, n2, o);
        }
        if (lane == 0) {
            float cn = acc[3];
            t1 = 1.f - d1 / fmaxf(sqrtf(n1) * cn, 1e-8f);
            t2 = fmaxf(d2 / fmaxf(sqrtf(n2) * cn, 1e-8f), 0.f);
        }
    }
    __shared__ float sh1[8], sh2[8];
    if (lane == 0) { sh1[warp] = t1; sh2[warp] = t2; }
    __syncthreads();
    if (threadIdx.x == 0) {
        float a = 0.f, b = 0.f;
        #pragma unroll
        for (int w = 0; w < 8; w++) { a += sh1[w]; b += sh2[w]; }
        atomicAdd(&acc[1], a);
        atomicAdd(&acc[2], b);
    }
}
__global__ void final_kernel(const float* __restrict__ acc, float* __restrict__ out)
{
    out[0] = acc[0] * (1.0f / (SROWS * OUTF)) + acc[1] * (1.0f / NROWS) + acc[2] * (1.0f / NROWS);
}

// ---- host ----
static inline int cdiv(int a, int b) { return (a + b - 1) / b; }

extern "C" void kernel_launch(void* const* d_in, const int* in_sizes, int n_in,
                              void* d_out_v, int out_size)
{
    (void)in_sizes; (void)n_in; (void)out_size;
    const float* x        = (const float*)d_in[0];
    const float* y        = (const float*)d_in[1];
    const int*   adj_rows = (const int*)d_in[2];
    const int*   adj_cols = (const int*)d_in[3];
    const float* adj_vals = (const float*)d_in[4];
    const int*   agg_rows = (const int*)d_in[5];
    const float* agg_vals = (const float*)d_in[6];
    const int*   perm     = (const int*)d_in[7];
    const float* mlp_W = (const float*)d_in[8],  *mlp_b = (const float*)d_in[9];
    const float* bn_gamma = (const float*)d_in[10], *bn_beta = (const float*)d_in[11];
    const float* hg_W1 = (const float*)d_in[12], *hg_b1 = (const float*)d_in[13];
    const float* hg_W2 = (const float*)d_in[14], *hg_b2 = (const float*)d_in[15];
    const float* hg_prelu = (const float*)d_in[16];
    const float* pred_W = (const float*)d_in[17], *pred_b = (const float*)d_in[18];
    const float* dgi_W = (const float*)d_in[19],  *dgi_b = (const float*)d_in[20];
    const float* dgi_prelu = (const float*)d_in[21];

    float* out = (float*)d_out_v;
    float* xp  = out + 1;

    __nv_bfloat16 *ah,*al,*h0h,*h0l,*th,*tl,*hh,*hl,*w;
    float *z,*zd,*s1,*s2,*agg,*stats,*scale,*shift,*cbuf,*acc,*eval;
    int *rowptr,*cnt,*ecol,*ecolp;
    cudaGetSymbolAddress((void**)&ah, g_ah);   cudaGetSymbolAddress((void**)&al, g_al);
    cudaGetSymbolAddress((void**)&h0h, g_h0h); cudaGetSymbolAddress((void**)&h0l, g_h0l);
    cudaGetSymbolAddress((void**)&th, g_th);   cudaGetSymbolAddress((void**)&tl, g_tl);
    cudaGetSymbolAddress((void**)&hh, g_hh);   cudaGetSymbolAddress((void**)&hl, g_hl);
    cudaGetSymbolAddress((void**)&z, g_z);     cudaGetSymbolAddress((void**)&zd, g_zd);
    cudaGetSymbolAddress((void**)&s1, g_s1);   cudaGetSymbolAddress((void**)&s2, g_s2);
    cudaGetSymbolAddress((void**)&agg, g_agg); cudaGetSymbolAddress((void**)&w, g_w);
    cudaGetSymbolAddress((void**)&stats, g_stats); cudaGetSymbolAddress((void**)&scale, g_scale);
    cudaGetSymbolAddress((void**)&shift, g_shift); cudaGetSymbolAddress((void**)&cbuf, g_c);
    cudaGetSymbolAddress((void**)&acc, g_acc);
    cudaGetSymbolAddress((void**)&rowptr, g_rowptr); cudaGetSymbolAddress((void**)&cnt, g_cnt);
    cudaGetSymbolAddress((void**)&ecol, g_ecol);     cudaGetSymbolAddress((void**)&ecolp, g_ecolp);
    cudaGetSymbolAddress((void**)&eval, g_eval);

    // side streams + events, created once (resource handles only; identical work per call)
    static cudaStream_t sB = nullptr, sC = nullptr, sD = nullptr;
    static cudaEvent_t eFork, eWts, eH0, eZD, eC, eD;
    if (sB == nullptr) {
        cudaStreamCreateWithFlags(&sB, cudaStreamNonBlocking);
        cudaStreamCreateWithFlags(&sC, cudaStreamNonBlocking);
        cudaStreamCreateWithFlags(&sD, cudaStreamNonBlocking);
        cudaEventCreateWithFlags(&eFork, cudaEventDisableTiming);
        cudaEventCreateWithFlags(&eWts,  cudaEventDisableTiming);
        cudaEventCreateWithFlags(&eH0,   cudaEventDisableTiming);
        cudaEventCreateWithFlags(&eZD,   cudaEventDisableTiming);
        cudaEventCreateWithFlags(&eC,    cudaEventDisableTiming);
        cudaEventCreateWithFlags(&eD,    cudaEventDisableTiming);
    }

    cudaStream_t st = 0;
    const int SMEM = 122880;  // 3 stages x 40960B
    cudaFuncSetAttribute(mma_gemm_kernel<ACT_NONE>, cudaFuncAttributeMaxDynamicSharedMemorySize, SMEM);
    cudaFuncSetAttribute(mma_gemm_kernel<ACT_LEAKY>, cudaFuncAttributeMaxDynamicSharedMemorySize, SMEM);
    const int MT = cdiv(NROWS, 128);                 // 391
    const dim3 gH(cdiv(HIDD, 128), MT);
    const dim3 gO(cdiv(OUTF, 128), MT);

    // ---- stream0 prologue: memsets + fork ----
    cudaMemsetAsync(acc, 0, 4 * sizeof(float), st);
    cudaMemsetAsync(agg, 0, (size_t)SROWS * OUTF * sizeof(float), st);
    cudaMemsetAsync(stats, 0, 2 * HIDD * sizeof(float), st);
    cudaEventRecord(eFork, st);

    // ---- stream B: small weight transposes + CSR build (independent of MLP) ----
    cudaStreamWaitEvent(sB, eFork, 0);
    wtrans_kernel<<<cdiv(HIDD * HIDD, 256), 256, 0, sB>>>(hg_W1, w + OFF_HG1, w + OFF_HG1 + SZ_HG, HIDD, HIDD);
    wtrans_kernel<<<cdiv(HIDD * HIDD, 256), 256, 0, sB>>>(hg_W2, w + OFF_HG2, w + OFF_HG2 + SZ_HG, HIDD, HIDD);
    wtrans_kernel<<<cdiv(HIDD * OUTF, 256), 256, 0, sB>>>(pred_W, w + OFF_PRED, w + OFF_PRED + SZ_PD, HIDD, OUTF);
    wtrans_kernel<<<cdiv(HIDD * OUTF, 256), 256, 0, sB>>>(dgi_W, w + OFF_DGI, w + OFF_DGI + SZ_PD, HIDD, OUTF);
    cudaMemsetAsync(cnt, 0, NROWS * sizeof(int), sB);
    hist_kernel<<<cdiv(NNZE, 256), 256, 0, sB>>>(adj_rows, cnt);
    scan_kernel<<<1, 1024, 0, sB>>>(cnt, rowptr);
    cudaMemsetAsync(cnt, 0, NROWS * sizeof(int), sB);
    scatter_kernel<<<cdiv(NNZE, 256), 256, 0, sB>>>(adj_rows, adj_cols, adj_vals, perm, rowptr, cnt, ecol, eval, ecolp);
    cudaEventRecord(eWts, sB);

    // ---- stream0: MLP chain ----
    split4_kernel<<<cdiv(NROWS * FIN / 4, 256), 256, 0, st>>>((const float4*)x, ah, al, NROWS * FIN / 4);
    wtrans_kernel<<<cdiv(FIN * HIDD, 256), 256, 0, st>>>(mlp_W, w + OFF_MLP, w + OFF_MLP + SZ_MLP, FIN, HIDD);
    mma_gemm_kernel<ACT_LEAKY><<<gH, 256, SMEM, st>>>(ah, al, w + OFF_MLP, w + OFF_MLP + SZ_MLP, mlp_b, z, NROWS, HIDD, FIN, 0.1f);
    bn_stats_kernel<<<256, 256, 0, st>>>(z, stats);
    bn_finalize_kernel<<<1, HIDD, 0, st>>>(stats, bn_gamma, bn_beta, scale, shift);
    bn_apply_split_kernel<<<cdiv(NROWS * HIDD / 4, 256), 256, 0, st>>>((const float4*)z, h0h, h0l, scale, shift);
    cudaEventRecord(eH0, st);

    // ---- stream C: DGI chain (overlaps HG1/HG2/pred on stream0) ----
    cudaStreamWaitEvent(sC, eH0, 0);
    cudaStreamWaitEvent(sC, eWts, 0);
    mma_gemm_kernel<ACT_NONE><<<gO, 256, SMEM, sC>>>(h0h, h0l, w + OFF_DGI, w + OFF_DGI + SZ_PD, dgi_b, zd, NROWS, OUTF, HIDD, 0.f);
    cudaEventRecord(eZD, sC);
    spmm_csr_kernel<OUTF, ACT_PRELU, false><<<NROWS, 288, 0, sC>>>(rowptr, ecol, eval, zd, s1, nullptr, nullptr, 0.f, dgi_prelu);
    cudaMemsetAsync(cbuf, 0, OUTF * sizeof(float), sC);
    colsum_kernel<<<256, 256, 0, sC>>>(s1, cbuf);
    c_finalize_kernel<<<1, 512, 0, sC>>>(cbuf, acc);
    cudaEventRecord(eC, sC);

    // ---- stream D: second DGI spmm (overlaps first) ----
    cudaStreamWaitEvent(sD, eZD, 0);
    spmm_csr_kernel<OUTF, ACT_PRELU, false><<<NROWS, 288, 0, sD>>>(rowptr, ecolp, eval, zd, s2, nullptr, nullptr, 0.f, dgi_prelu);
    cudaEventRecord(eD, sD);

    // ---- stream0: HG1 -> HG2 -> pred -> MSE ----
    cudaStreamWaitEvent(st, eWts, 0);
    mma_gemm_kernel<ACT_NONE><<<gH, 256, SMEM, st>>>(h0h, h0l, w + OFF_HG1, w + OFF_HG1 + SZ_HG, hg_b1, z, NROWS, HIDD, HIDD, 0.f);
    spmm_csr_kernel<HIDD, ACT_PRELU, true><<<NROWS, 256, 0, st>>>(rowptr, ecol, eval, z, nullptr, th, tl, 0.f, hg_prelu);
    mma_gemm_kernel<ACT_NONE><<<gH, 256, SMEM, st>>>(th, tl, w + OFF_HG2, w + OFF_HG2 + SZ_HG, hg_b2, z, NROWS, HIDD, HIDD, 0.f);
    spmm_csr_kernel<HIDD, ACT_LEAKY, true><<<NROWS, 256, 0, st>>>(rowptr, ecol, eval, z, nullptr, hh, hl, 0.01f, nullptr);
    mma_gemm_kernel<ACT_LEAKY><<<gO, 256, SMEM, st>>>(hh, hl, w + OFF_PRED, w + OFF_PRED + SZ_PD, pred_b, xp, NROWS, OUTF, HIDD, 0.01f);
    agg_kernel<<<cdiv(NROWS * OUTF, 256), 256, 0, st>>>(agg_rows, agg_vals, xp, agg);
    mse_kernel<<<2048, 256, 0, st>>>(agg, y, acc);

    // ---- join + epilogue ----
    cudaStreamWaitEvent(st, eC, 0);
    cudaStreamWaitEvent(st, eD, 0);
    cos_kernel<<<cdiv(NROWS, 8), 256, 0, st>>>(s1, s2, cbuf, acc);
    final_kernel<<<1, 1, 0, st>>>(acc, out);
}